// round 1
// baseline (speedup 1.0000x reference)
#include <cuda_runtime.h>
#include <cstdint>
#include <cstddef>

#define NN   10000
#define NE   320000
#define FIN5 5
#define FOUT 64
#define CC   27
#define MLPH 32
#define HID  450
#define FDIM 128

// ---------------- scratch (static device globals; no allocation) ----------------
__device__ float g_msg[(size_t)NE * FOUT];   // 81.92 MB per-edge messages
__device__ float g_x1[NN * FOUT];            // NNConv output (pre/post relu)
__device__ float g_xl[NN * CC];              // GAT transformed features
__device__ float g_asrc[NN];
__device__ float g_adst[NN];
__device__ float g_x2[NN * CC];              // GAT output (relu'd) == v
__device__ float g_h450[HID];
__device__ int   g_deg[NN];
__device__ int   g_rowptr[NN + 1];
__device__ int   g_pos[NN];
__device__ int   g_eid[NE];

__device__ __forceinline__ float leaky(float v) { return v > 0.f ? v : 0.2f * v; }

// ---------------- init: zero deg, seed h450 with fc1 bias ----------------
__global__ void k_init(const float* __restrict__ fc1_b) {
    int i = blockIdx.x * blockDim.x + threadIdx.x;
    if (i < NN)  g_deg[i] = 0;
    if (i < HID) g_h450[i] = fc1_b[i];
}

// ---------------- CSR build (by dst) ----------------
__global__ void k_hist(const int* __restrict__ dst) {
    int e = blockIdx.x * blockDim.x + threadIdx.x;
    if (e < NE) atomicAdd(&g_deg[dst[e]], 1);
}

__global__ void k_scan() {
    // single block of 1024 threads, 10 elements per thread
    const int CH = 10;
    int tid = threadIdx.x;
    int base = tid * CH;
    int local[CH];
    int s = 0;
#pragma unroll
    for (int k = 0; k < CH; k++) {
        int idx = base + k;
        int d = (idx < NN) ? g_deg[idx] : 0;
        local[k] = s;
        s += d;
    }
    int lane = tid & 31, wid = tid >> 5;
    int v = s;
#pragma unroll
    for (int o = 1; o < 32; o <<= 1) {
        int t = __shfl_up_sync(0xFFFFFFFFu, v, o);
        if (lane >= o) v += t;
    }
    __shared__ int ws[32];
    if (lane == 31) ws[wid] = v;
    __syncthreads();
    if (wid == 0) {
        int u = ws[lane];
#pragma unroll
        for (int o = 1; o < 32; o <<= 1) {
            int t = __shfl_up_sync(0xFFFFFFFFu, u, o);
            if (lane >= o) u += t;
        }
        ws[lane] = u;
    }
    __syncthreads();
    int excl = v - s + (wid > 0 ? ws[wid - 1] : 0);
#pragma unroll
    for (int k = 0; k < CH; k++) {
        int idx = base + k;
        if (idx <= NN) {
            int val = excl + local[k];
            g_rowptr[idx] = val;
            if (idx < NN) g_pos[idx] = val;
        }
    }
}

__global__ void k_scatter(const int* __restrict__ dst) {
    int e = blockIdx.x * blockDim.x + threadIdx.x;
    if (e < NE) {
        int p = atomicAdd(&g_pos[dst[e]], 1);
        g_eid[p] = e;
    }
}

// ---------------- NNConv root term: x1 = x @ nn_root + nn_bias ----------------
__global__ void k_root(const float* __restrict__ x, const float* __restrict__ nr,
                       const float* __restrict__ nb) {
    int t = blockIdx.x * blockDim.x + threadIdx.x;
    if (t >= NN * FOUT) return;
    int n = t >> 6, o = t & 63;
    float acc = nb[o];
#pragma unroll
    for (int i = 0; i < FIN5; i++) acc = fmaf(x[n * FIN5 + i], nr[i * FOUT + o], acc);
    g_x1[t] = acc;
}

// ---------------- per-edge message (hot kernel, packed f32x2 FMA) ----------------
__global__ void __launch_bounds__(128) k_msg(const float* __restrict__ x,
                                             const int* __restrict__ src,
                                             const float* __restrict__ ea,
                                             const float* __restrict__ w1,
                                             const float* __restrict__ b1,
                                             const float* __restrict__ w2,
                                             const float* __restrict__ b2) {
    __shared__ __align__(16) float w2s[MLPH * FIN5 * FOUT];   // 40 KB
    __shared__ float w1s[2 * MLPH];
    __shared__ float b1s[MLPH];
    __shared__ float b2s[FIN5 * FOUT];
    int tid = threadIdx.x;
    for (int i = tid; i < MLPH * FIN5 * FOUT; i += 128) w2s[i] = w2[i];
    if (tid < 64) w1s[tid] = w1[tid];
    if (tid < 32) b1s[tid] = b1[tid];
    for (int i = tid; i < FIN5 * FOUT; i += 128) b2s[i] = b2[i];
    __syncthreads();

    int e = blockIdx.x * 128 + tid;
    if (e >= NE) return;

    int s = src[e];
    float2 eav = ((const float2*)ea)[e];
    float xs[FIN5];
#pragma unroll
    for (int i = 0; i < FIN5; i++) xs[i] = x[s * FIN5 + i];

    unsigned long long acc[32];
    // init with bias term: msg[o] = sum_i xs[i]*b2[i*64+o]
#pragma unroll
    for (int o2 = 0; o2 < 32; o2++) {
        float a0 = 0.f, a1 = 0.f;
#pragma unroll
        for (int i = 0; i < FIN5; i++) {
            a0 = fmaf(xs[i], b2s[i * FOUT + 2 * o2], a0);
            a1 = fmaf(xs[i], b2s[i * FOUT + 2 * o2 + 1], a1);
        }
        asm("mov.b64 %0,{%1,%2};" : "=l"(acc[o2]) : "f"(a0), "f"(a1));
    }

#pragma unroll 1
    for (int m = 0; m < MLPH; m++) {
        float h = fmaf(eav.x, w1s[m], fmaf(eav.y, w1s[MLPH + m], b1s[m]));
        h = fmaxf(h, 0.f);
#pragma unroll
        for (int i = 0; i < FIN5; i++) {
            float a = h * xs[i];
            unsigned long long a2;
            asm("mov.b64 %0,{%1,%1};" : "=l"(a2) : "f"(a));
            const ulonglong2* wrow = (const ulonglong2*)(w2s + m * (FIN5 * FOUT) + i * FOUT);
#pragma unroll
            for (int q = 0; q < 16; q++) {
                ulonglong2 w = wrow[q];
                asm("fma.rn.f32x2 %0,%1,%2,%0;" : "+l"(acc[2 * q])     : "l"(a2), "l"(w.x));
                asm("fma.rn.f32x2 %0,%1,%2,%0;" : "+l"(acc[2 * q + 1]) : "l"(a2), "l"(w.y));
            }
        }
    }

    float2* out = (float2*)&g_msg[(size_t)e * FOUT];
#pragma unroll
    for (int o2 = 0; o2 < 32; o2++) out[o2] = *(float2*)&acc[o2];
}

// ---------------- gather-reduce msgs into x1, relu ----------------
__global__ void k_agg() {
    int gw = (blockIdx.x * blockDim.x + threadIdx.x) >> 5;
    int lane = threadIdx.x & 31;
    if (gw >= NN) return;
    int n = gw;
    float a0 = g_x1[n * FOUT + lane];
    float a1 = g_x1[n * FOUT + 32 + lane];
    int beg = g_rowptr[n], end = g_rowptr[n + 1];
    for (int j = beg; j < end; j++) {
        int e = g_eid[j];
        const float* mrow = &g_msg[(size_t)e * FOUT];
        a0 += mrow[lane];
        a1 += mrow[32 + lane];
    }
    g_x1[n * FOUT + lane] = fmaxf(a0, 0.f);
    g_x1[n * FOUT + 32 + lane] = fmaxf(a1, 0.f);
}

// ---------------- GAT prep: xl = x1 @ gat_w ; a_src/a_dst dots ----------------
__global__ void k_gatprep(const float* __restrict__ gw, const float* __restrict__ att_s,
                          const float* __restrict__ att_d) {
    __shared__ float gws[FOUT * CC];
    __shared__ float as_s[CC], ad_s[CC];
    int tid = threadIdx.x;
    for (int i = tid; i < FOUT * CC; i += blockDim.x) gws[i] = gw[i];
    if (tid < CC) { as_s[tid] = att_s[tid]; ad_s[tid] = att_d[tid]; }
    __syncthreads();

    int gwarp = (blockIdx.x * blockDim.x + tid) >> 5;
    int lane = tid & 31;
    if (gwarp >= NN) return;
    int n = gwarp;
    float acc = 0.f;
    if (lane < CC) {
#pragma unroll 4
        for (int k = 0; k < FOUT; k++) acc = fmaf(g_x1[n * FOUT + k], gws[k * CC + lane], acc);
        g_xl[n * CC + lane] = acc;
    }
    float vs = (lane < CC) ? acc * as_s[lane] : 0.f;
    float vd = (lane < CC) ? acc * ad_s[lane] : 0.f;
#pragma unroll
    for (int o = 16; o > 0; o >>= 1) {
        vs += __shfl_down_sync(0xFFFFFFFFu, vs, o);
        vd += __shfl_down_sync(0xFFFFFFFFu, vd, o);
    }
    if (lane == 0) { g_asrc[n] = vs; g_adst[n] = vd; }
}

// ---------------- GAT softmax-aggregate (with self loop), relu+bias ----------------
__global__ void k_gat(const int* __restrict__ src, const float* __restrict__ gbias) {
    __shared__ float bias_s[CC];
    int tid = threadIdx.x;
    if (tid < CC) bias_s[tid] = gbias[tid];
    __syncthreads();

    int gwarp = (blockIdx.x * blockDim.x + tid) >> 5;
    int lane = tid & 31;
    if (gwarp >= NN) return;
    int n = gwarp;
    float asn = g_asrc[n], adn = g_adst[n];
    int beg = g_rowptr[n], end = g_rowptr[n + 1];

    // pass 1: max
    float self_a = leaky(asn + adn);
    float mx = self_a;
    for (int j = beg + lane; j < end; j += 32) {
        int e = g_eid[j];
        int s = src[e];
        mx = fmaxf(mx, leaky(g_asrc[s] + adn));
    }
#pragma unroll
    for (int o = 16; o > 0; o >>= 1) mx = fmaxf(mx, __shfl_xor_sync(0xFFFFFFFFu, mx, o));

    // pass 2: batched 32-wide loads, shuffle-broadcast accumulate
    float w0 = expf(self_a - mx);
    float denom = (lane == 0) ? w0 : 0.f;
    float acc = (lane < CC) ? w0 * g_xl[n * CC + lane] : 0.f;
    for (int j0 = beg; j0 < end; j0 += 32) {
        int j = j0 + lane;
        int s = 0;
        float w = 0.f;
        if (j < end) {
            int e = g_eid[j];
            s = src[e];
            w = expf(leaky(g_asrc[s] + adn) - mx);
        }
        denom += w;
        int cnt = min(32, end - j0);
        for (int t = 0; t < cnt; t++) {
            float wt = __shfl_sync(0xFFFFFFFFu, w, t);
            int st = __shfl_sync(0xFFFFFFFFu, s, t);
            if (lane < CC) acc = fmaf(wt, g_xl[st * CC + lane], acc);
        }
    }
#pragma unroll
    for (int o = 16; o > 0; o >>= 1) denom += __shfl_xor_sync(0xFFFFFFFFu, denom, o);
    if (lane < CC) g_x2[n * CC + lane] = fmaxf(acc / denom + bias_s[lane], 0.f);
}

// ---------------- fc1: v[270000] @ W[270000,450]  (HBM streaming) ----------------
__global__ void __launch_bounds__(480) k_fc1(const float* __restrict__ W) {
    const long TOT = (long)NN * CC;  // 270000
    int t = threadIdx.x;
    long r0 = (long)blockIdx.x * 512;
    long r1 = r0 + 512;
    if (r1 > TOT) r1 = TOT;
    if (t >= HID) return;
    float a0 = 0.f, a1 = 0.f, a2 = 0.f, a3 = 0.f;
    long r = r0;
    for (; r + 4 <= r1; r += 4) {
        a0 = fmaf(g_x2[r],     W[(size_t)r * HID + t],       a0);
        a1 = fmaf(g_x2[r + 1], W[(size_t)(r + 1) * HID + t], a1);
        a2 = fmaf(g_x2[r + 2], W[(size_t)(r + 2) * HID + t], a2);
        a3 = fmaf(g_x2[r + 3], W[(size_t)(r + 3) * HID + t], a3);
    }
    for (; r < r1; r++) a0 = fmaf(g_x2[r], W[(size_t)r * HID + t], a0);
    atomicAdd(&g_h450[t], (a0 + a1) + (a2 + a3));
}

// ---------------- fc2: relu(h450) @ W[450,128] + b, relu ----------------
__global__ void k_fc2(const float* __restrict__ W, const float* __restrict__ b,
                      float* __restrict__ out) {
    __shared__ float hs[HID];
    int t = threadIdx.x;
    for (int j = t; j < HID; j += FDIM) hs[j] = fmaxf(g_h450[j], 0.f);
    __syncthreads();
    float acc = b[t];
#pragma unroll 4
    for (int j = 0; j < HID; j++) acc = fmaf(hs[j], W[j * FDIM + t], acc);
    out[t] = fmaxf(acc, 0.f);
}

// ---------------- launch ----------------
extern "C" void kernel_launch(void* const* d_in, const int* in_sizes, int n_in,
                              void* d_out, int out_size) {
    const float* x       = (const float*)d_in[0];
    const int*   eidx    = (const int*)d_in[1];
    const float* eattr   = (const float*)d_in[2];
    const float* mlp_w1  = (const float*)d_in[3];
    const float* mlp_b1  = (const float*)d_in[4];
    const float* mlp_w2  = (const float*)d_in[5];
    const float* mlp_b2  = (const float*)d_in[6];
    const float* nn_root = (const float*)d_in[7];
    const float* nn_bias = (const float*)d_in[8];
    const float* gat_w   = (const float*)d_in[9];
    const float* att_src = (const float*)d_in[10];
    const float* att_dst = (const float*)d_in[11];
    const float* gat_b   = (const float*)d_in[12];
    const float* fc1_w   = (const float*)d_in[13];
    const float* fc1_b   = (const float*)d_in[14];
    const float* fc2_w   = (const float*)d_in[15];
    const float* fc2_b   = (const float*)d_in[16];
    float* out = (float*)d_out;

    const int* src = eidx;          // edge_index[0]
    const int* dst = eidx + NE;     // edge_index[1]

    k_init<<<(NN + 255) / 256, 256>>>(fc1_b);
    k_hist<<<(NE + 255) / 256, 256>>>(dst);
    k_scan<<<1, 1024>>>();
    k_scatter<<<(NE + 255) / 256, 256>>>(dst);
    k_root<<<(NN * FOUT + 255) / 256, 256>>>(x, nn_root, nn_bias);
    k_msg<<<(NE + 127) / 128, 128>>>(x, src, eattr, mlp_w1, mlp_b1, mlp_w2, mlp_b2);
    k_agg<<<(NN * 32 + 255) / 256, 256>>>();
    k_gatprep<<<(NN * 32 + 255) / 256, 256>>>(gat_w, att_src, att_dst);
    k_gat<<<(NN * 32 + 255) / 256, 256>>>(src, gat_b);
    k_fc1<<<((NN * CC) + 511) / 512, 480>>>(fc1_w);
    k_fc2<<<1, FDIM>>>(fc2_w, fc2_b, out);
}

// round 2
// speedup vs baseline: 1.9164x; 1.9164x over previous
#include <cuda_runtime.h>
#include <cstdint>
#include <cstddef>

#define NN   10000
#define NE   320000
#define FIN5 5
#define FOUT 64
#define CC   27
#define MLPH 32
#define HID  450
#define FDIM 128

// ---------------- scratch (static device globals; no allocation) ----------------
__device__ float g_pn[(size_t)NN * 160];     // per-node reduced outer products  [n][i*32+m]
__device__ float g_sx[NN * FIN5];            // per-node sum of x[src] over in-edges
__device__ float g_x1[NN * FOUT];            // NNConv output (post relu)
__device__ float g_xl[NN * CC];              // GAT transformed features
__device__ float g_asrc[NN];
__device__ float g_adst[NN];
__device__ float g_x2[NN * CC];              // GAT output (relu'd) == v
__device__ float g_h450[HID];
__device__ int   g_deg[NN];
__device__ int   g_rowptr[NN + 1];
__device__ int   g_pos[NN];
__device__ int   g_eid[NE];

__device__ __forceinline__ float leaky(float v) { return v > 0.f ? v : 0.2f * v; }

// ---------------- init: zero deg, seed h450 with fc1 bias ----------------
__global__ void k_init(const float* __restrict__ fc1_b) {
    int i = blockIdx.x * blockDim.x + threadIdx.x;
    if (i < NN)  g_deg[i] = 0;
    if (i < HID) g_h450[i] = fc1_b[i];
}

// ---------------- CSR build (by dst) ----------------
__global__ void k_hist(const int* __restrict__ dst) {
    int e = blockIdx.x * blockDim.x + threadIdx.x;
    if (e < NE) atomicAdd(&g_deg[dst[e]], 1);
}

__global__ void k_scan() {
    const int CH = 10;
    int tid = threadIdx.x;
    int base = tid * CH;
    int local[CH];
    int s = 0;
#pragma unroll
    for (int k = 0; k < CH; k++) {
        int idx = base + k;
        int d = (idx < NN) ? g_deg[idx] : 0;
        local[k] = s;
        s += d;
    }
    int lane = tid & 31, wid = tid >> 5;
    int v = s;
#pragma unroll
    for (int o = 1; o < 32; o <<= 1) {
        int t = __shfl_up_sync(0xFFFFFFFFu, v, o);
        if (lane >= o) v += t;
    }
    __shared__ int ws[32];
    if (lane == 31) ws[wid] = v;
    __syncthreads();
    if (wid == 0) {
        int u = ws[lane];
#pragma unroll
        for (int o = 1; o < 32; o <<= 1) {
            int t = __shfl_up_sync(0xFFFFFFFFu, u, o);
            if (lane >= o) u += t;
        }
        ws[lane] = u;
    }
    __syncthreads();
    int excl = v - s + (wid > 0 ? ws[wid - 1] : 0);
#pragma unroll
    for (int k = 0; k < CH; k++) {
        int idx = base + k;
        if (idx <= NN) {
            int val = excl + local[k];
            g_rowptr[idx] = val;
            if (idx < NN) g_pos[idx] = val;
        }
    }
}

__global__ void k_scatter(const int* __restrict__ dst) {
    int e = blockIdx.x * blockDim.x + threadIdx.x;
    if (e < NE) {
        int p = atomicAdd(&g_pos[dst[e]], 1);
        g_eid[p] = e;
    }
}

// ---------------- fused per-edge MLP + rank-1 outer-product reduce by dst ----------------
// Pn[n][i*32+m] = sum_{e->n} relu(ea@W1+b1)[m] * x[src_e, i]
// Sx[n][i]      = sum_{e->n} x[src_e, i]
__global__ void k_edgeagg(const int* __restrict__ src, const float* __restrict__ x,
                          const float* __restrict__ ea, const float* __restrict__ w1,
                          const float* __restrict__ b1) {
    int gwarp = (blockIdx.x * blockDim.x + threadIdx.x) >> 5;
    int lane = threadIdx.x & 31;
    if (gwarp >= NN) return;
    int n = gwarp;

    // lane m's W1 column and bias
    float w1a = w1[lane], w1b = w1[MLPH + lane], b1v = b1[lane];

    float a0 = 0.f, a1 = 0.f, a2 = 0.f, a3 = 0.f, a4 = 0.f;      // Pn accumulators (m = lane)
    float s0 = 0.f, s1 = 0.f, s2 = 0.f, s3 = 0.f, s4 = 0.f;      // Sx partials

    int beg = g_rowptr[n], end = g_rowptr[n + 1];
    for (int j0 = beg; j0 < end; j0 += 32) {
        int j = j0 + lane;
        float ax = 0.f, ay = 0.f, x0 = 0.f, x1v = 0.f, x2v = 0.f, x3v = 0.f, x4v = 0.f;
        if (j < end) {
            int e = g_eid[j];
            int sN = src[e];
            float2 eav = ((const float2*)ea)[e];
            ax = eav.x; ay = eav.y;
            const float* xp = x + sN * FIN5;
            x0 = xp[0]; x1v = xp[1]; x2v = xp[2]; x3v = xp[3]; x4v = xp[4];
        }
        s0 += x0; s1 += x1v; s2 += x2v; s3 += x3v; s4 += x4v;
        int cnt = min(32, end - j0);
        for (int t = 0; t < cnt; t++) {
            float tax = __shfl_sync(0xFFFFFFFFu, ax, t);
            float tay = __shfl_sync(0xFFFFFFFFu, ay, t);
            float h = fmaxf(fmaf(tax, w1a, fmaf(tay, w1b, b1v)), 0.f);
            a0 = fmaf(h, __shfl_sync(0xFFFFFFFFu, x0,  t), a0);
            a1 = fmaf(h, __shfl_sync(0xFFFFFFFFu, x1v, t), a1);
            a2 = fmaf(h, __shfl_sync(0xFFFFFFFFu, x2v, t), a2);
            a3 = fmaf(h, __shfl_sync(0xFFFFFFFFu, x3v, t), a3);
            a4 = fmaf(h, __shfl_sync(0xFFFFFFFFu, x4v, t), a4);
        }
    }

    float* p = &g_pn[(size_t)n * 160];
    p[0 * 32 + lane] = a0;
    p[1 * 32 + lane] = a1;
    p[2 * 32 + lane] = a2;
    p[3 * 32 + lane] = a3;
    p[4 * 32 + lane] = a4;

#pragma unroll
    for (int o = 16; o > 0; o >>= 1) {
        s0 += __shfl_xor_sync(0xFFFFFFFFu, s0, o);
        s1 += __shfl_xor_sync(0xFFFFFFFFu, s1, o);
        s2 += __shfl_xor_sync(0xFFFFFFFFu, s2, o);
        s3 += __shfl_xor_sync(0xFFFFFFFFu, s3, o);
        s4 += __shfl_xor_sync(0xFFFFFFFFu, s4, o);
    }
    if (lane == 0) {
        float* sx = &g_sx[n * FIN5];
        sx[0] = s0; sx[1] = s1; sx[2] = s2; sx[3] = s3; sx[4] = s4;
    }
}

// ---------------- x1 = relu( Pn @ W2 + Sx @ b2 + x @ root + bias ) ----------------
__global__ void __launch_bounds__(256) k_x1(const float* __restrict__ x,
                                            const float* __restrict__ w2,
                                            const float* __restrict__ b2,
                                            const float* __restrict__ nr,
                                            const float* __restrict__ nb) {
    __shared__ __align__(16) float w2s[MLPH * FIN5 * FOUT];   // 40 KB, layout m*320+i*64+o
    __shared__ float b2s[FIN5 * FOUT];
    __shared__ float nrs[FIN5 * FOUT];
    __shared__ float nbs[FOUT];
    int tid = threadIdx.x;
    for (int i = tid; i < MLPH * FIN5 * FOUT; i += 256) w2s[i] = w2[i];
    for (int i = tid; i < FIN5 * FOUT; i += 256) { b2s[i] = b2[i]; nrs[i] = nr[i]; }
    if (tid < FOUT) nbs[tid] = nb[tid];
    __syncthreads();

    int gwarp = (blockIdx.x * 256 + tid) >> 5;
    int lane = tid & 31;
    if (gwarp >= NN) return;
    int n = gwarp;

    const float* p = &g_pn[(size_t)n * 160];
    float p0 = p[0 * 32 + lane], p1 = p[1 * 32 + lane], p2 = p[2 * 32 + lane],
          p3 = p[3 * 32 + lane], p4 = p[4 * 32 + lane];

    float acc0 = nbs[lane], acc1 = nbs[32 + lane];
    // root + b2 terms (warp-uniform broadcast loads)
#pragma unroll
    for (int i = 0; i < FIN5; i++) {
        float xv = __ldg(&x[n * FIN5 + i]);
        float sxv = g_sx[n * FIN5 + i];
        acc0 = fmaf(xv, nrs[i * FOUT + lane], acc0);
        acc1 = fmaf(xv, nrs[i * FOUT + 32 + lane], acc1);
        acc0 = fmaf(sxv, b2s[i * FOUT + lane], acc0);
        acc1 = fmaf(sxv, b2s[i * FOUT + 32 + lane], acc1);
    }
    // Pn @ W2
#pragma unroll 4
    for (int m = 0; m < MLPH; m++) {
        float v0 = __shfl_sync(0xFFFFFFFFu, p0, m);
        float v1 = __shfl_sync(0xFFFFFFFFu, p1, m);
        float v2 = __shfl_sync(0xFFFFFFFFu, p2, m);
        float v3 = __shfl_sync(0xFFFFFFFFu, p3, m);
        float v4 = __shfl_sync(0xFFFFFFFFu, p4, m);
        const float* wrow = &w2s[m * (FIN5 * FOUT)];
        acc0 = fmaf(v0, wrow[0 * FOUT + lane], acc0);
        acc1 = fmaf(v0, wrow[0 * FOUT + 32 + lane], acc1);
        acc0 = fmaf(v1, wrow[1 * FOUT + lane], acc0);
        acc1 = fmaf(v1, wrow[1 * FOUT + 32 + lane], acc1);
        acc0 = fmaf(v2, wrow[2 * FOUT + lane], acc0);
        acc1 = fmaf(v2, wrow[2 * FOUT + 32 + lane], acc1);
        acc0 = fmaf(v3, wrow[3 * FOUT + lane], acc0);
        acc1 = fmaf(v3, wrow[3 * FOUT + 32 + lane], acc1);
        acc0 = fmaf(v4, wrow[4 * FOUT + lane], acc0);
        acc1 = fmaf(v4, wrow[4 * FOUT + 32 + lane], acc1);
    }
    g_x1[n * FOUT + lane]      = fmaxf(acc0, 0.f);
    g_x1[n * FOUT + 32 + lane] = fmaxf(acc1, 0.f);
}

// ---------------- GAT prep: xl = x1 @ gat_w ; a_src/a_dst dots ----------------
__global__ void k_gatprep(const float* __restrict__ gw, const float* __restrict__ att_s,
                          const float* __restrict__ att_d) {
    __shared__ float gws[FOUT * CC];
    __shared__ float as_s[CC], ad_s[CC];
    int tid = threadIdx.x;
    for (int i = tid; i < FOUT * CC; i += blockDim.x) gws[i] = gw[i];
    if (tid < CC) { as_s[tid] = att_s[tid]; ad_s[tid] = att_d[tid]; }
    __syncthreads();

    int gwarp = (blockIdx.x * blockDim.x + tid) >> 5;
    int lane = tid & 31;
    if (gwarp >= NN) return;
    int n = gwarp;
    float acc = 0.f;
    if (lane < CC) {
#pragma unroll 4
        for (int k = 0; k < FOUT; k++) acc = fmaf(g_x1[n * FOUT + k], gws[k * CC + lane], acc);
        g_xl[n * CC + lane] = acc;
    }
    float vs = (lane < CC) ? acc * as_s[lane] : 0.f;
    float vd = (lane < CC) ? acc * ad_s[lane] : 0.f;
#pragma unroll
    for (int o = 16; o > 0; o >>= 1) {
        vs += __shfl_down_sync(0xFFFFFFFFu, vs, o);
        vd += __shfl_down_sync(0xFFFFFFFFu, vd, o);
    }
    if (lane == 0) { g_asrc[n] = vs; g_adst[n] = vd; }
}

// ---------------- GAT softmax-aggregate (with self loop), relu+bias ----------------
__global__ void k_gat(const int* __restrict__ src, const float* __restrict__ gbias) {
    __shared__ float bias_s[CC];
    int tid = threadIdx.x;
    if (tid < CC) bias_s[tid] = gbias[tid];
    __syncthreads();

    int gwarp = (blockIdx.x * blockDim.x + tid) >> 5;
    int lane = tid & 31;
    if (gwarp >= NN) return;
    int n = gwarp;
    float asn = g_asrc[n], adn = g_adst[n];
    int beg = g_rowptr[n], end = g_rowptr[n + 1];

    float self_a = leaky(asn + adn);
    float mx = self_a;
    for (int j = beg + lane; j < end; j += 32) {
        int e = g_eid[j];
        int s = src[e];
        mx = fmaxf(mx, leaky(g_asrc[s] + adn));
    }
#pragma unroll
    for (int o = 16; o > 0; o >>= 1) mx = fmaxf(mx, __shfl_xor_sync(0xFFFFFFFFu, mx, o));

    float w0 = expf(self_a - mx);
    float denom = (lane == 0) ? w0 : 0.f;
    float acc = (lane < CC) ? w0 * g_xl[n * CC + lane] : 0.f;
    for (int j0 = beg; j0 < end; j0 += 32) {
        int j = j0 + lane;
        int s = 0;
        float w = 0.f;
        if (j < end) {
            int e = g_eid[j];
            s = src[e];
            w = expf(leaky(g_asrc[s] + adn) - mx);
        }
        denom += w;
        int cnt = min(32, end - j0);
        for (int t = 0; t < cnt; t++) {
            float wt = __shfl_sync(0xFFFFFFFFu, w, t);
            int st = __shfl_sync(0xFFFFFFFFu, s, t);
            if (lane < CC) acc = fmaf(wt, g_xl[st * CC + lane], acc);
        }
    }
#pragma unroll
    for (int o = 16; o > 0; o >>= 1) denom += __shfl_xor_sync(0xFFFFFFFFu, denom, o);
    if (lane < CC) g_x2[n * CC + lane] = fmaxf(acc / denom + bias_s[lane], 0.f);
}

// ---------------- fc1: v[270000] @ W[270000,450]  (HBM streaming) ----------------
__global__ void __launch_bounds__(480) k_fc1(const float* __restrict__ W) {
    const long TOT = (long)NN * CC;  // 270000
    const int ROWS = 256;
    int t = threadIdx.x;
    long r0 = (long)blockIdx.x * ROWS;
    long r1 = r0 + ROWS;
    if (r1 > TOT) r1 = TOT;
    if (t >= HID) return;
    float a0 = 0.f, a1 = 0.f, a2 = 0.f, a3 = 0.f;
    long r = r0;
    for (; r + 4 <= r1; r += 4) {
        a0 = fmaf(g_x2[r],     W[(size_t)r * HID + t],       a0);
        a1 = fmaf(g_x2[r + 1], W[(size_t)(r + 1) * HID + t], a1);
        a2 = fmaf(g_x2[r + 2], W[(size_t)(r + 2) * HID + t], a2);
        a3 = fmaf(g_x2[r + 3], W[(size_t)(r + 3) * HID + t], a3);
    }
    for (; r < r1; r++) a0 = fmaf(g_x2[r], W[(size_t)r * HID + t], a0);
    atomicAdd(&g_h450[t], (a0 + a1) + (a2 + a3));
}

// ---------------- fc2: relu(h450) @ W[450,128] + b, relu ----------------
__global__ void k_fc2(const float* __restrict__ W, const float* __restrict__ b,
                      float* __restrict__ out) {
    __shared__ float hs[HID];
    int t = threadIdx.x;
    for (int j = t; j < HID; j += FDIM) hs[j] = fmaxf(g_h450[j], 0.f);
    __syncthreads();
    float acc = b[t];
#pragma unroll 4
    for (int j = 0; j < HID; j++) acc = fmaf(hs[j], W[j * FDIM + t], acc);
    out[t] = fmaxf(acc, 0.f);
}

// ---------------- launch ----------------
extern "C" void kernel_launch(void* const* d_in, const int* in_sizes, int n_in,
                              void* d_out, int out_size) {
    const float* x       = (const float*)d_in[0];
    const int*   eidx    = (const int*)d_in[1];
    const float* eattr   = (const float*)d_in[2];
    const float* mlp_w1  = (const float*)d_in[3];
    const float* mlp_b1  = (const float*)d_in[4];
    const float* mlp_w2  = (const float*)d_in[5];
    const float* mlp_b2  = (const float*)d_in[6];
    const float* nn_root = (const float*)d_in[7];
    const float* nn_bias = (const float*)d_in[8];
    const float* gat_w   = (const float*)d_in[9];
    const float* att_src = (const float*)d_in[10];
    const float* att_dst = (const float*)d_in[11];
    const float* gat_b   = (const float*)d_in[12];
    const float* fc1_w   = (const float*)d_in[13];
    const float* fc1_b   = (const float*)d_in[14];
    const float* fc2_w   = (const float*)d_in[15];
    const float* fc2_b   = (const float*)d_in[16];
    float* out = (float*)d_out;

    const int* src = eidx;          // edge_index[0]
    const int* dst = eidx + NE;     // edge_index[1]

    k_init<<<(NN + 255) / 256, 256>>>(fc1_b);
    k_hist<<<(NE + 255) / 256, 256>>>(dst);
    k_scan<<<1, 1024>>>();
    k_scatter<<<(NE + 255) / 256, 256>>>(dst);
    k_edgeagg<<<(NN * 32 + 255) / 256, 256>>>(src, x, eattr, mlp_w1, mlp_b1);
    k_x1<<<(NN * 32 + 255) / 256, 256>>>(x, mlp_w2, mlp_b2, nn_root, nn_bias);
    k_gatprep<<<(NN * 32 + 255) / 256, 256>>>(gat_w, att_src, att_dst);
    k_gat<<<(NN * 32 + 255) / 256, 256>>>(src, gat_b);
    k_fc1<<<((NN * CC) + 255) / 256, 480>>>(fc1_w);
    k_fc2<<<1, FDIM>>>(fc2_w, fc2_b, out);
}

// round 3
// speedup vs baseline: 1.9858x; 1.0362x over previous
#include <cuda_runtime.h>
#include <cstdint>
#include <cstddef>

#define NN   10000
#define NE   320000
#define FIN5 5
#define FOUT 64
#define CC   27
#define MLPH 32
#define HID  450
#define FDIM 128

// ---------------- scratch (static device globals; no allocation) ----------------
__device__ float g_pn[(size_t)NN * 160];     // per-node reduced outer products  [n][i*32+m]
__device__ float g_sx[NN * FIN5];            // per-node sum of x[src] over in-edges
__device__ float g_xl[NN * CC];              // GAT transformed features
__device__ float g_asrc[NN];
__device__ float g_adst[NN];
__device__ float g_x2[NN * CC];              // GAT output (relu'd) == v
__device__ float g_h450[HID];                // fc1 accumulator (zeroed by k_scan each call)
__device__ int   g_deg[NN];                  // zeroed by k_scan each call (after use)
__device__ int   g_rowptr[NN + 1];
__device__ int   g_pos[NN];
__device__ int   g_eid[NE];

__device__ __forceinline__ float leaky(float v) { return v > 0.f ? v : 0.2f * v; }

// ---------------- CSR build (by dst) ----------------
__global__ void k_hist(const int* __restrict__ dst) {
    int e = blockIdx.x * blockDim.x + threadIdx.x;
    if (e < NE) atomicAdd(&g_deg[dst[e]], 1);
}

// exclusive scan of deg -> rowptr/pos; then re-zero deg and h450 for next call
__global__ void k_scan() {
    const int CH = 10;
    int tid = threadIdx.x;
    int base = tid * CH;
    int local[CH];
    int s = 0;
#pragma unroll
    for (int k = 0; k < CH; k++) {
        int idx = base + k;
        int d = (idx < NN) ? g_deg[idx] : 0;
        local[k] = s;
        s += d;
    }
    int lane = tid & 31, wid = tid >> 5;
    int v = s;
#pragma unroll
    for (int o = 1; o < 32; o <<= 1) {
        int t = __shfl_up_sync(0xFFFFFFFFu, v, o);
        if (lane >= o) v += t;
    }
    __shared__ int ws[32];
    if (lane == 31) ws[wid] = v;
    __syncthreads();
    if (wid == 0) {
        int u = ws[lane];
#pragma unroll
        for (int o = 1; o < 32; o <<= 1) {
            int t = __shfl_up_sync(0xFFFFFFFFu, u, o);
            if (lane >= o) u += t;
        }
        ws[lane] = u;
    }
    __syncthreads();
    int excl = v - s + (wid > 0 ? ws[wid - 1] : 0);
#pragma unroll
    for (int k = 0; k < CH; k++) {
        int idx = base + k;
        if (idx <= NN) {
            int val = excl + local[k];
            g_rowptr[idx] = val;
            if (idx < NN) g_pos[idx] = val;
        }
    }
    __syncthreads();
    // reset for next call (deg consumed above; h450 consumed by fc1/fc2 later this call,
    // but those run AFTER this kernel within the same call, so zero now is correct:
    // fc1 accumulates into zeros, fc2 reads, and next call's scan re-zeroes again)
    for (int i = tid; i < NN; i += 1024) g_deg[i] = 0;
    if (tid < HID) g_h450[tid] = 0.f;
}

__global__ void k_scatter(const int* __restrict__ dst) {
    int e = blockIdx.x * blockDim.x + threadIdx.x;
    if (e < NE) {
        int p = atomicAdd(&g_pos[dst[e]], 1);
        g_eid[p] = e;
    }
}

// ---------------- fused per-edge MLP + rank-1 outer-product reduce by dst ----------------
__global__ void k_edgeagg(const int* __restrict__ src, const float* __restrict__ x,
                          const float* __restrict__ ea, const float* __restrict__ w1,
                          const float* __restrict__ b1) {
    int gwarp = (blockIdx.x * blockDim.x + threadIdx.x) >> 5;
    int lane = threadIdx.x & 31;
    if (gwarp >= NN) return;
    int n = gwarp;

    float w1a = w1[lane], w1b = w1[MLPH + lane], b1v = b1[lane];

    float a0 = 0.f, a1 = 0.f, a2 = 0.f, a3 = 0.f, a4 = 0.f;
    float s0 = 0.f, s1 = 0.f, s2 = 0.f, s3 = 0.f, s4 = 0.f;

    int beg = g_rowptr[n], end = g_rowptr[n + 1];
    for (int j0 = beg; j0 < end; j0 += 32) {
        int j = j0 + lane;
        float ax = 0.f, ay = 0.f, x0 = 0.f, x1v = 0.f, x2v = 0.f, x3v = 0.f, x4v = 0.f;
        if (j < end) {
            int e = g_eid[j];
            int sN = src[e];
            float2 eav = ((const float2*)ea)[e];
            ax = eav.x; ay = eav.y;
            const float* xp = x + sN * FIN5;
            x0 = xp[0]; x1v = xp[1]; x2v = xp[2]; x3v = xp[3]; x4v = xp[4];
        }
        s0 += x0; s1 += x1v; s2 += x2v; s3 += x3v; s4 += x4v;
        int cnt = min(32, end - j0);
        for (int t = 0; t < cnt; t++) {
            float tax = __shfl_sync(0xFFFFFFFFu, ax, t);
            float tay = __shfl_sync(0xFFFFFFFFu, ay, t);
            float h = fmaxf(fmaf(tax, w1a, fmaf(tay, w1b, b1v)), 0.f);
            a0 = fmaf(h, __shfl_sync(0xFFFFFFFFu, x0,  t), a0);
            a1 = fmaf(h, __shfl_sync(0xFFFFFFFFu, x1v, t), a1);
            a2 = fmaf(h, __shfl_sync(0xFFFFFFFFu, x2v, t), a2);
            a3 = fmaf(h, __shfl_sync(0xFFFFFFFFu, x3v, t), a3);
            a4 = fmaf(h, __shfl_sync(0xFFFFFFFFu, x4v, t), a4);
        }
    }

    float* p = &g_pn[(size_t)n * 160];
    p[0 * 32 + lane] = a0;
    p[1 * 32 + lane] = a1;
    p[2 * 32 + lane] = a2;
    p[3 * 32 + lane] = a3;
    p[4 * 32 + lane] = a4;

#pragma unroll
    for (int o = 16; o > 0; o >>= 1) {
        s0 += __shfl_xor_sync(0xFFFFFFFFu, s0, o);
        s1 += __shfl_xor_sync(0xFFFFFFFFu, s1, o);
        s2 += __shfl_xor_sync(0xFFFFFFFFu, s2, o);
        s3 += __shfl_xor_sync(0xFFFFFFFFu, s3, o);
        s4 += __shfl_xor_sync(0xFFFFFFFFu, s4, o);
    }
    if (lane == 0) {
        float* sx = &g_sx[n * FIN5];
        sx[0] = s0; sx[1] = s1; sx[2] = s2; sx[3] = s3; sx[4] = s4;
    }
}

// ---- fused: x1 = relu(Pn@W2 + Sx@b2 + x@root + bias); xl = x1@gat_w; a_src/a_dst ----
__global__ void __launch_bounds__(256) k_x1gat(const float* __restrict__ x,
                                               const float* __restrict__ w2,
                                               const float* __restrict__ b2,
                                               const float* __restrict__ nr,
                                               const float* __restrict__ nb,
                                               const float* __restrict__ gw,
                                               const float* __restrict__ att_s,
                                               const float* __restrict__ att_d) {
    __shared__ __align__(16) float w2s[MLPH * FIN5 * FOUT];   // 40 KB
    __shared__ float b2s[FIN5 * FOUT];
    __shared__ float nrs[FIN5 * FOUT];
    __shared__ float nbs[FOUT];
    __shared__ float gws[FOUT * CC];                          // 6.75 KB
    __shared__ float as_s[CC], ad_s[CC];
    int tid = threadIdx.x;
    for (int i = tid; i < MLPH * FIN5 * FOUT; i += 256) w2s[i] = w2[i];
    for (int i = tid; i < FIN5 * FOUT; i += 256) { b2s[i] = b2[i]; nrs[i] = nr[i]; }
    if (tid < FOUT) nbs[tid] = nb[tid];
    for (int i = tid; i < FOUT * CC; i += 256) gws[i] = gw[i];
    if (tid < CC) { as_s[tid] = att_s[tid]; ad_s[tid] = att_d[tid]; }
    __syncthreads();

    int gwarp = (blockIdx.x * 256 + tid) >> 5;
    int lane = tid & 31;
    if (gwarp >= NN) return;
    int n = gwarp;

    const float* p = &g_pn[(size_t)n * 160];
    float p0 = p[0 * 32 + lane], p1 = p[1 * 32 + lane], p2 = p[2 * 32 + lane],
          p3 = p[3 * 32 + lane], p4 = p[4 * 32 + lane];

    float acc0 = nbs[lane], acc1 = nbs[32 + lane];
#pragma unroll
    for (int i = 0; i < FIN5; i++) {
        float xv = __ldg(&x[n * FIN5 + i]);
        float sxv = g_sx[n * FIN5 + i];
        acc0 = fmaf(xv, nrs[i * FOUT + lane], acc0);
        acc1 = fmaf(xv, nrs[i * FOUT + 32 + lane], acc1);
        acc0 = fmaf(sxv, b2s[i * FOUT + lane], acc0);
        acc1 = fmaf(sxv, b2s[i * FOUT + 32 + lane], acc1);
    }
#pragma unroll 4
    for (int m = 0; m < MLPH; m++) {
        float v0 = __shfl_sync(0xFFFFFFFFu, p0, m);
        float v1 = __shfl_sync(0xFFFFFFFFu, p1, m);
        float v2 = __shfl_sync(0xFFFFFFFFu, p2, m);
        float v3 = __shfl_sync(0xFFFFFFFFu, p3, m);
        float v4 = __shfl_sync(0xFFFFFFFFu, p4, m);
        const float* wrow = &w2s[m * (FIN5 * FOUT)];
        acc0 = fmaf(v0, wrow[0 * FOUT + lane], acc0);
        acc1 = fmaf(v0, wrow[0 * FOUT + 32 + lane], acc1);
        acc0 = fmaf(v1, wrow[1 * FOUT + lane], acc0);
        acc1 = fmaf(v1, wrow[1 * FOUT + 32 + lane], acc1);
        acc0 = fmaf(v2, wrow[2 * FOUT + lane], acc0);
        acc1 = fmaf(v2, wrow[2 * FOUT + 32 + lane], acc1);
        acc0 = fmaf(v3, wrow[3 * FOUT + lane], acc0);
        acc1 = fmaf(v3, wrow[3 * FOUT + 32 + lane], acc1);
        acc0 = fmaf(v4, wrow[4 * FOUT + lane], acc0);
        acc1 = fmaf(v4, wrow[4 * FOUT + 32 + lane], acc1);
    }
    float x1a = fmaxf(acc0, 0.f);
    float x1b = fmaxf(acc1, 0.f);

    // xl[n, c] = sum_k x1[n,k] * gw[k, c]   (c = lane, valid for lane < CC)
    float xv = 0.f;
#pragma unroll 8
    for (int k = 0; k < 32; k++) {
        float va = __shfl_sync(0xFFFFFFFFu, x1a, k);
        float vb = __shfl_sync(0xFFFFFFFFu, x1b, k);
        xv = fmaf(va, gws[k * CC + lane % CC], xv);           // lane>=27 computes garbage
        xv = fmaf(vb, gws[(32 + k) * CC + lane % CC], xv);
    }
    if (lane < CC) g_xl[n * CC + lane] = xv;

    float vs = (lane < CC) ? xv * as_s[lane] : 0.f;
    float vd = (lane < CC) ? xv * ad_s[lane] : 0.f;
#pragma unroll
    for (int o = 16; o > 0; o >>= 1) {
        vs += __shfl_down_sync(0xFFFFFFFFu, vs, o);
        vd += __shfl_down_sync(0xFFFFFFFFu, vd, o);
    }
    if (lane == 0) { g_asrc[n] = vs; g_adst[n] = vd; }
}

// ---------------- GAT softmax-aggregate (with self loop), relu+bias ----------------
__global__ void k_gat(const int* __restrict__ src, const float* __restrict__ gbias) {
    __shared__ float bias_s[CC];
    int tid = threadIdx.x;
    if (tid < CC) bias_s[tid] = gbias[tid];
    __syncthreads();

    int gwarp = (blockIdx.x * blockDim.x + tid) >> 5;
    int lane = tid & 31;
    if (gwarp >= NN) return;
    int n = gwarp;
    float asn = g_asrc[n], adn = g_adst[n];
    int beg = g_rowptr[n], end = g_rowptr[n + 1];

    float self_a = leaky(asn + adn);
    float mx = self_a;
    for (int j = beg + lane; j < end; j += 32) {
        int e = g_eid[j];
        int s = src[e];
        mx = fmaxf(mx, leaky(g_asrc[s] + adn));
    }
#pragma unroll
    for (int o = 16; o > 0; o >>= 1) mx = fmaxf(mx, __shfl_xor_sync(0xFFFFFFFFu, mx, o));

    float w0 = expf(self_a - mx);
    float denom = (lane == 0) ? w0 : 0.f;
    float acc = (lane < CC) ? w0 * g_xl[n * CC + lane] : 0.f;
    for (int j0 = beg; j0 < end; j0 += 32) {
        int j = j0 + lane;
        int s = 0;
        float w = 0.f;
        if (j < end) {
            int e = g_eid[j];
            s = src[e];
            w = expf(leaky(g_asrc[s] + adn) - mx);
        }
        denom += w;
        int cnt = min(32, end - j0);
        for (int t = 0; t < cnt; t++) {
            float wt = __shfl_sync(0xFFFFFFFFu, w, t);
            int st = __shfl_sync(0xFFFFFFFFu, s, t);
            if (lane < CC) acc = fmaf(wt, g_xl[st * CC + lane], acc);
        }
    }
#pragma unroll
    for (int o = 16; o > 0; o >>= 1) denom += __shfl_xor_sync(0xFFFFFFFFu, denom, o);
    if (lane < CC) g_x2[n * CC + lane] = fmaxf(acc / denom + bias_s[lane], 0.f);
}

// ---------------- fc1 with zero-row skip (v is ~50% zeros after relu) ----------------
__global__ void __launch_bounds__(480) k_fc1(const float* __restrict__ W) {
    const int TOT = NN * CC;  // 270000
    const int ROWS = 256;
    int t = threadIdx.x;
    int r0 = blockIdx.x * ROWS;
    int r1 = min(r0 + ROWS, TOT);
    if (t >= HID) return;
    float a0 = 0.f, a1 = 0.f;
#pragma unroll 4
    for (int r = r0; r + 2 <= r1; r += 2) {
        float v0 = g_x2[r];
        float v1 = g_x2[r + 1];
        if (v0 != 0.f) a0 = fmaf(v0, W[(size_t)r * HID + t], a0);
        if (v1 != 0.f) a1 = fmaf(v1, W[(size_t)(r + 1) * HID + t], a1);
    }
    if ((r1 - r0) & 1) {
        float v = g_x2[r1 - 1];
        if (v != 0.f) a0 = fmaf(v, W[(size_t)(r1 - 1) * HID + t], a0);
    }
    atomicAdd(&g_h450[t], a0 + a1);
}

// ---------------- fc2: relu(h450 + fc1_b) @ W[450,128] + b, relu ----------------
__global__ void k_fc2(const float* __restrict__ W, const float* __restrict__ b,
                      const float* __restrict__ fc1b, float* __restrict__ out) {
    __shared__ float hs[HID];
    int t = threadIdx.x;
    for (int j = t; j < HID; j += FDIM) hs[j] = fmaxf(g_h450[j] + fc1b[j], 0.f);
    __syncthreads();
    float acc = b[t];
#pragma unroll 4
    for (int j = 0; j < HID; j++) acc = fmaf(hs[j], W[j * FDIM + t], acc);
    out[t] = fmaxf(acc, 0.f);
}

// ---------------- launch ----------------
extern "C" void kernel_launch(void* const* d_in, const int* in_sizes, int n_in,
                              void* d_out, int out_size) {
    const float* x       = (const float*)d_in[0];
    const int*   eidx    = (const int*)d_in[1];
    const float* eattr   = (const float*)d_in[2];
    const float* mlp_w1  = (const float*)d_in[3];
    const float* mlp_b1  = (const float*)d_in[4];
    const float* mlp_w2  = (const float*)d_in[5];
    const float* mlp_b2  = (const float*)d_in[6];
    const float* nn_root = (const float*)d_in[7];
    const float* nn_bias = (const float*)d_in[8];
    const float* gat_w   = (const float*)d_in[9];
    const float* att_src = (const float*)d_in[10];
    const float* att_dst = (const float*)d_in[11];
    const float* gat_b   = (const float*)d_in[12];
    const float* fc1_w   = (const float*)d_in[13];
    const float* fc1_b   = (const float*)d_in[14];
    const float* fc2_w   = (const float*)d_in[15];
    const float* fc2_b   = (const float*)d_in[16];
    float* out = (float*)d_out;

    const int* src = eidx;          // edge_index[0]
    const int* dst = eidx + NE;     // edge_index[1]

    k_hist<<<(NE + 255) / 256, 256>>>(dst);
    k_scan<<<1, 1024>>>();
    k_scatter<<<(NE + 255) / 256, 256>>>(dst);
    k_edgeagg<<<(NN * 32 + 255) / 256, 256>>>(src, x, eattr, mlp_w1, mlp_b1);
    k_x1gat<<<(NN * 32 + 255) / 256, 256>>>(x, mlp_w2, mlp_b2, nn_root, nn_bias,
                                            gat_w, att_src, att_dst);
    k_gat<<<(NN * 32 + 255) / 256, 256>>>(src, gat_b);
    k_fc1<<<((NN * CC) + 255) / 256, 480>>>(fc1_w);
    k_fc2<<<1, FDIM>>>(fc2_w, fc2_b, fc1_b, out);
}

// round 5
// speedup vs baseline: 2.1253x; 1.0702x over previous
#include <cuda_runtime.h>
#include <cstdint>
#include <cstddef>

#define NN   10000
#define NE   320000
#define FIN5 5
#define FOUT 64
#define CC   27
#define MLPH 32
#define HID  450
#define FDIM 128

// ---------------- scratch (static device globals; no allocation) ----------------
__device__ float g_pn[(size_t)NN * 160];     // per-node reduced outer products  [n][i*32+m]
__device__ float g_sx[NN * FIN5];            // per-node sum of x[src] over in-edges
__device__ float g_xl[NN * CC];              // GAT transformed features
__device__ float g_asrc[NN];
__device__ float g_adst[NN];
__device__ float g_x2[NN * CC];              // GAT output (relu'd) == v
__device__ float g_h450[HID];                // fc1 accumulator (zeroed by k_scan each call)
__device__ int   g_deg[NN];                  // zeroed by k_scan each call (after use)
__device__ int   g_rowptr[NN + 1];
__device__ int   g_pos[NN];
__device__ int   g_eid[NE];
__device__ int   g_nz[NN];                   // per-node nonzero count of x2
__device__ int   g_nzoff[NN + 1];            // scanned offsets
__device__ __align__(16) float g_cv[NN * CC];  // compacted values
__device__ __align__(16) int   g_ci[NN * CC];  // compacted row indices

__device__ __forceinline__ float leaky(float v) { return v > 0.f ? v : 0.2f * v; }

// ---------------- CSR build (by dst) ----------------
__global__ void k_hist(const int* __restrict__ dst) {
    int e = blockIdx.x * blockDim.x + threadIdx.x;
    if (e < NE) atomicAdd(&g_deg[dst[e]], 1);
}

// exclusive scan of deg -> rowptr/pos; re-zero deg and h450 for this call
__global__ void k_scan() {
    const int CH = 10;
    int tid = threadIdx.x;
    int base = tid * CH;
    int local[CH];
    int s = 0;
#pragma unroll
    for (int k = 0; k < CH; k++) {
        int idx = base + k;
        int d = (idx < NN) ? g_deg[idx] : 0;
        local[k] = s;
        s += d;
    }
    int lane = tid & 31, wid = tid >> 5;
    int v = s;
#pragma unroll
    for (int o = 1; o < 32; o <<= 1) {
        int t = __shfl_up_sync(0xFFFFFFFFu, v, o);
        if (lane >= o) v += t;
    }
    __shared__ int ws[32];
    if (lane == 31) ws[wid] = v;
    __syncthreads();
    if (wid == 0) {
        int u = ws[lane];
#pragma unroll
        for (int o = 1; o < 32; o <<= 1) {
            int t = __shfl_up_sync(0xFFFFFFFFu, u, o);
            if (lane >= o) u += t;
        }
        ws[lane] = u;
    }
    __syncthreads();
    int excl = v - s + (wid > 0 ? ws[wid - 1] : 0);
#pragma unroll
    for (int k = 0; k < CH; k++) {
        int idx = base + k;
        if (idx <= NN) {
            int val = excl + local[k];
            g_rowptr[idx] = val;
            if (idx < NN) g_pos[idx] = val;
        }
    }
    __syncthreads();
    for (int i = tid; i < NN; i += 1024) g_deg[i] = 0;
    if (tid < HID) g_h450[tid] = 0.f;
}

__global__ void k_scatter(const int* __restrict__ dst) {
    int e = blockIdx.x * blockDim.x + threadIdx.x;
    if (e < NE) {
        int p = atomicAdd(&g_pos[dst[e]], 1);
        g_eid[p] = e;
    }
}

// ---------------- fused per-edge MLP + rank-1 outer-product reduce by dst ----------------
__global__ void k_edgeagg(const int* __restrict__ src, const float* __restrict__ x,
                          const float* __restrict__ ea, const float* __restrict__ w1,
                          const float* __restrict__ b1) {
    int gwarp = (blockIdx.x * blockDim.x + threadIdx.x) >> 5;
    int lane = threadIdx.x & 31;
    if (gwarp >= NN) return;
    int n = gwarp;

    float w1a = w1[lane], w1b = w1[MLPH + lane], b1v = b1[lane];

    float a0 = 0.f, a1 = 0.f, a2 = 0.f, a3 = 0.f, a4 = 0.f;
    float s0 = 0.f, s1 = 0.f, s2 = 0.f, s3 = 0.f, s4 = 0.f;

    int beg = g_rowptr[n], end = g_rowptr[n + 1];
    for (int j0 = beg; j0 < end; j0 += 32) {
        int j = j0 + lane;
        float ax = 0.f, ay = 0.f, x0 = 0.f, x1v = 0.f, x2v = 0.f, x3v = 0.f, x4v = 0.f;
        if (j < end) {
            int e = g_eid[j];
            int sN = src[e];
            float2 eav = ((const float2*)ea)[e];
            ax = eav.x; ay = eav.y;
            const float* xp = x + sN * FIN5;
            x0 = xp[0]; x1v = xp[1]; x2v = xp[2]; x3v = xp[3]; x4v = xp[4];
        }
        s0 += x0; s1 += x1v; s2 += x2v; s3 += x3v; s4 += x4v;
        int cnt = min(32, end - j0);
        for (int t = 0; t < cnt; t++) {
            float tax = __shfl_sync(0xFFFFFFFFu, ax, t);
            float tay = __shfl_sync(0xFFFFFFFFu, ay, t);
            float h = fmaxf(fmaf(tax, w1a, fmaf(tay, w1b, b1v)), 0.f);
            a0 = fmaf(h, __shfl_sync(0xFFFFFFFFu, x0,  t), a0);
            a1 = fmaf(h, __shfl_sync(0xFFFFFFFFu, x1v, t), a1);
            a2 = fmaf(h, __shfl_sync(0xFFFFFFFFu, x2v, t), a2);
            a3 = fmaf(h, __shfl_sync(0xFFFFFFFFu, x3v, t), a3);
            a4 = fmaf(h, __shfl_sync(0xFFFFFFFFu, x4v, t), a4);
        }
    }

    float* p = &g_pn[(size_t)n * 160];
    p[0 * 32 + lane] = a0;
    p[1 * 32 + lane] = a1;
    p[2 * 32 + lane] = a2;
    p[3 * 32 + lane] = a3;
    p[4 * 32 + lane] = a4;

#pragma unroll
    for (int o = 16; o > 0; o >>= 1) {
        s0 += __shfl_xor_sync(0xFFFFFFFFu, s0, o);
        s1 += __shfl_xor_sync(0xFFFFFFFFu, s1, o);
        s2 += __shfl_xor_sync(0xFFFFFFFFu, s2, o);
        s3 += __shfl_xor_sync(0xFFFFFFFFu, s3, o);
        s4 += __shfl_xor_sync(0xFFFFFFFFu, s4, o);
    }
    if (lane == 0) {
        float* sx = &g_sx[n * FIN5];
        sx[0] = s0; sx[1] = s1; sx[2] = s2; sx[3] = s3; sx[4] = s4;
    }
}

// ---- fused: x1 = relu(Pn@W2 + Sx@b2 + x@root + bias); xl = x1@gat_w; a_src/a_dst ----
__global__ void __launch_bounds__(256) k_x1gat(const float* __restrict__ x,
                                               const float* __restrict__ w2,
                                               const float* __restrict__ b2,
                                               const float* __restrict__ nr,
                                               const float* __restrict__ nb,
                                               const float* __restrict__ gw,
                                               const float* __restrict__ att_s,
                                               const float* __restrict__ att_d) {
    __shared__ __align__(16) float w2s[MLPH * FIN5 * FOUT];   // 40 KB
    __shared__ float b2s[FIN5 * FOUT];
    __shared__ float nrs[FIN5 * FOUT];
    __shared__ float nbs[FOUT];
    __shared__ float gws[FOUT * CC];
    __shared__ float as_s[CC], ad_s[CC];
    int tid = threadIdx.x;
    for (int i = tid; i < MLPH * FIN5 * FOUT; i += 256) w2s[i] = w2[i];
    for (int i = tid; i < FIN5 * FOUT; i += 256) { b2s[i] = b2[i]; nrs[i] = nr[i]; }
    if (tid < FOUT) nbs[tid] = nb[tid];
    for (int i = tid; i < FOUT * CC; i += 256) gws[i] = gw[i];
    if (tid < CC) { as_s[tid] = att_s[tid]; ad_s[tid] = att_d[tid]; }
    __syncthreads();

    int gwarp = (blockIdx.x * 256 + tid) >> 5;
    int lane = tid & 31;
    if (gwarp >= NN) return;
    int n = gwarp;

    const float* p = &g_pn[(size_t)n * 160];
    float p0 = p[0 * 32 + lane], p1 = p[1 * 32 + lane], p2 = p[2 * 32 + lane],
          p3 = p[3 * 32 + lane], p4 = p[4 * 32 + lane];

    float acc0 = nbs[lane], acc1 = nbs[32 + lane];
#pragma unroll
    for (int i = 0; i < FIN5; i++) {
        float xv = __ldg(&x[n * FIN5 + i]);
        float sxv = g_sx[n * FIN5 + i];
        acc0 = fmaf(xv, nrs[i * FOUT + lane], acc0);
        acc1 = fmaf(xv, nrs[i * FOUT + 32 + lane], acc1);
        acc0 = fmaf(sxv, b2s[i * FOUT + lane], acc0);
        acc1 = fmaf(sxv, b2s[i * FOUT + 32 + lane], acc1);
    }
#pragma unroll 4
    for (int m = 0; m < MLPH; m++) {
        float v0 = __shfl_sync(0xFFFFFFFFu, p0, m);
        float v1 = __shfl_sync(0xFFFFFFFFu, p1, m);
        float v2 = __shfl_sync(0xFFFFFFFFu, p2, m);
        float v3 = __shfl_sync(0xFFFFFFFFu, p3, m);
        float v4 = __shfl_sync(0xFFFFFFFFu, p4, m);
        const float* wrow = &w2s[m * (FIN5 * FOUT)];
        acc0 = fmaf(v0, wrow[0 * FOUT + lane], acc0);
        acc1 = fmaf(v0, wrow[0 * FOUT + 32 + lane], acc1);
        acc0 = fmaf(v1, wrow[1 * FOUT + lane], acc0);
        acc1 = fmaf(v1, wrow[1 * FOUT + 32 + lane], acc1);
        acc0 = fmaf(v2, wrow[2 * FOUT + lane], acc0);
        acc1 = fmaf(v2, wrow[2 * FOUT + 32 + lane], acc1);
        acc0 = fmaf(v3, wrow[3 * FOUT + lane], acc0);
        acc1 = fmaf(v3, wrow[3 * FOUT + 32 + lane], acc1);
        acc0 = fmaf(v4, wrow[4 * FOUT + lane], acc0);
        acc1 = fmaf(v4, wrow[4 * FOUT + 32 + lane], acc1);
    }
    float x1a = fmaxf(acc0, 0.f);
    float x1b = fmaxf(acc1, 0.f);

    float xv = 0.f;
#pragma unroll 8
    for (int k = 0; k < 32; k++) {
        float va = __shfl_sync(0xFFFFFFFFu, x1a, k);
        float vb = __shfl_sync(0xFFFFFFFFu, x1b, k);
        xv = fmaf(va, gws[k * CC + lane % CC], xv);
        xv = fmaf(vb, gws[(32 + k) * CC + lane % CC], xv);
    }
    if (lane < CC) g_xl[n * CC + lane] = xv;

    float vs = (lane < CC) ? xv * as_s[lane] : 0.f;
    float vd = (lane < CC) ? xv * ad_s[lane] : 0.f;
#pragma unroll
    for (int o = 16; o > 0; o >>= 1) {
        vs += __shfl_down_sync(0xFFFFFFFFu, vs, o);
        vd += __shfl_down_sync(0xFFFFFFFFu, vd, o);
    }
    if (lane == 0) { g_asrc[n] = vs; g_adst[n] = vd; }
}

// -------- GAT softmax-aggregate, single pass (no max shift; logits bounded) --------
// also emits per-node nonzero count of x2 for fc1 compaction
__global__ void k_gat(const int* __restrict__ src, const float* __restrict__ gbias) {
    __shared__ float bias_s[CC];
    int tid = threadIdx.x;
    if (tid < CC) bias_s[tid] = gbias[tid];
    __syncthreads();

    int gwarp = (blockIdx.x * blockDim.x + tid) >> 5;
    int lane = tid & 31;
    if (gwarp >= NN) return;
    int n = gwarp;
    float asn = g_asrc[n], adn = g_adst[n];
    int beg = g_rowptr[n], end = g_rowptr[n + 1];

    float w0 = __expf(leaky(asn + adn));                  // self loop
    float denom = (lane == 0) ? w0 : 0.f;
    float acc = (lane < CC) ? w0 * g_xl[n * CC + lane] : 0.f;
    for (int j0 = beg; j0 < end; j0 += 32) {
        int j = j0 + lane;
        int s = 0;
        float w = 0.f;
        if (j < end) {
            int e = g_eid[j];
            s = src[e];
            w = __expf(leaky(g_asrc[s] + adn));
        }
        denom += w;
        int cnt = min(32, end - j0);
        for (int t = 0; t < cnt; t++) {
            float wt = __shfl_sync(0xFFFFFFFFu, w, t);
            int st = __shfl_sync(0xFFFFFFFFu, s, t);
            if (lane < CC) acc = fmaf(wt, g_xl[st * CC + lane], acc);
        }
    }
#pragma unroll
    for (int o = 16; o > 0; o >>= 1) denom += __shfl_xor_sync(0xFFFFFFFFu, denom, o);
    float val = 0.f;
    if (lane < CC) {
        val = fmaxf(acc / denom + bias_s[lane], 0.f);
        g_x2[n * CC + lane] = val;
    }
    unsigned m = __ballot_sync(0xFFFFFFFFu, lane < CC && val > 0.f);
    if (lane == 0) g_nz[n] = __popc(m);
}

// ---------------- scan of nonzero counts -> g_nzoff ----------------
__global__ void k_nzscan() {
    const int CH = 10;
    int tid = threadIdx.x;
    int base = tid * CH;
    int local[CH];
    int s = 0;
#pragma unroll
    for (int k = 0; k < CH; k++) {
        int idx = base + k;
        int d = (idx < NN) ? g_nz[idx] : 0;
        local[k] = s;
        s += d;
    }
    int lane = tid & 31, wid = tid >> 5;
    int v = s;
#pragma unroll
    for (int o = 1; o < 32; o <<= 1) {
        int t = __shfl_up_sync(0xFFFFFFFFu, v, o);
        if (lane >= o) v += t;
    }
    __shared__ int ws[32];
    if (lane == 31) ws[wid] = v;
    __syncthreads();
    if (wid == 0) {
        int u = ws[lane];
#pragma unroll
        for (int o = 1; o < 32; o <<= 1) {
            int t = __shfl_up_sync(0xFFFFFFFFu, u, o);
            if (lane >= o) u += t;
        }
        ws[lane] = u;
    }
    __syncthreads();
    int excl = v - s + (wid > 0 ? ws[wid - 1] : 0);
#pragma unroll
    for (int k = 0; k < CH; k++) {
        int idx = base + k;
        if (idx <= NN) g_nzoff[idx] = excl + local[k];
    }
}

// ---------------- deterministic compaction (node order, ballot prefix) ----------------
__global__ void k_compact() {
    int gwarp = (blockIdx.x * blockDim.x + threadIdx.x) >> 5;
    int lane = threadIdx.x & 31;
    if (gwarp >= NN) return;
    int n = gwarp;
    int off = g_nzoff[n];
    float val = (lane < CC) ? g_x2[n * CC + lane] : 0.f;
    unsigned m = __ballot_sync(0xFFFFFFFFu, lane < CC && val > 0.f);
    if (lane < CC && val > 0.f) {
        int p = __popc(m & ((1u << lane) - 1u));
        g_cv[off + p] = val;
        g_ci[off + p] = n * CC + lane;
    }
}

// ---------------- fc1 over compacted nonzeros: branch-free, full MLP ----------------
__global__ void __launch_bounds__(480) k_fc1(const float* __restrict__ W) {
    const int ROWS = 256;
    int cnt = g_nzoff[NN];
    int k0 = blockIdx.x * ROWS;
    if (k0 >= cnt) return;
    int k1 = min(k0 + ROWS, cnt);
    int t = threadIdx.x;
    if (t >= HID) return;
    float a0 = 0.f, a1 = 0.f, a2 = 0.f, a3 = 0.f;
    int k = k0;
    for (; k + 4 <= k1; k += 4) {
        float4 v = *(const float4*)&g_cv[k];
        int4   r = *(const int4*)&g_ci[k];
        a0 = fmaf(v.x, W[(size_t)r.x * HID + t], a0);
        a1 = fmaf(v.y, W[(size_t)r.y * HID + t], a1);
        a2 = fmaf(v.z, W[(size_t)r.z * HID + t], a2);
        a3 = fmaf(v.w, W[(size_t)r.w * HID + t], a3);
    }
    for (; k < k1; k++) a0 = fmaf(g_cv[k], W[(size_t)g_ci[k] * HID + t], a0);
    atomicAdd(&g_h450[t], (a0 + a1) + (a2 + a3));
}

// ---------------- fc2: relu(h450 + fc1_b) @ W[450,128] + b, relu ----------------
__global__ void k_fc2(const float* __restrict__ W, const float* __restrict__ b,
                      const float* __restrict__ fc1b, float* __restrict__ out) {
    __shared__ float hs[HID];
    int t = threadIdx.x;
    for (int j = t; j < HID; j += FDIM) hs[j] = fmaxf(g_h450[j] + fc1b[j], 0.f);
    __syncthreads();
    float acc = b[t];
#pragma unroll 4
    for (int j = 0; j < HID; j++) acc = fmaf(hs[j], W[j * FDIM + t], acc);
    out[t] = fmaxf(acc, 0.f);
}

// ---------------- launch ----------------
extern "C" void kernel_launch(void* const* d_in, const int* in_sizes, int n_in,
                              void* d_out, int out_size) {
    const float* x       = (const float*)d_in[0];
    const int*   eidx    = (const int*)d_in[1];
    const float* eattr   = (const float*)d_in[2];
    const float* mlp_w1  = (const float*)d_in[3];
    const float* mlp_b1  = (const float*)d_in[4];
    const float* mlp_w2  = (const float*)d_in[5];
    const float* mlp_b2  = (const float*)d_in[6];
    const float* nn_root = (const float*)d_in[7];
    const float* nn_bias = (const float*)d_in[8];
    const float* gat_w   = (const float*)d_in[9];
    const float* att_src = (const float*)d_in[10];
    const float* att_dst = (const float*)d_in[11];
    const float* gat_b   = (const float*)d_in[12];
    const float* fc1_w   = (const float*)d_in[13];
    const float* fc1_b   = (const float*)d_in[14];
    const float* fc2_w   = (const float*)d_in[15];
    const float* fc2_b   = (const float*)d_in[16];
    float* out = (float*)d_out;

    const int* src = eidx;          // edge_index[0]
    const int* dst = eidx + NE;     // edge_index[1]

    k_hist<<<(NE + 255) / 256, 256>>>(dst);
    k_scan<<<1, 1024>>>();
    k_scatter<<<(NE + 255) / 256, 256>>>(dst);
    k_edgeagg<<<(NN * 32 + 255) / 256, 256>>>(src, x, eattr, mlp_w1, mlp_b1);
    k_x1gat<<<(NN * 32 + 255) / 256, 256>>>(x, mlp_w2, mlp_b2, nn_root, nn_bias,
                                            gat_w, att_src, att_dst);
    k_gat<<<(NN * 32 + 255) / 256, 256>>>(src, gat_b);
    k_nzscan<<<1, 1024>>>();
    k_compact<<<(NN * 32 + 255) / 256, 256>>>();
    k_fc1<<<((NN * CC) + 255) / 256, 480>>>(fc1_w);
    k_fc2<<<1, FDIM>>>(fc2_w, fc2_b, fc1_b, out);
}

// round 10
// speedup vs baseline: 2.8830x; 1.3565x over previous
#include <cuda_runtime.h>
#include <cstdint>
#include <cstddef>

#define NN   10000
#define NE   320000
#define FIN5 5
#define FOUT 64
#define CC   27
#define MLPH 32
#define HID  450
#define FDIM 128

// ---------------- scratch (static device globals; no allocation) ----------------
__device__ float g_pn[(size_t)NN * 160];     // per-node reduced outer products  [n][i*32+m]
__device__ float g_sx[NN * FIN5];            // per-node sum of x[src] over in-edges
__device__ float g_xl[NN * CC];              // GAT transformed features
__device__ float g_asrc[NN];
__device__ float g_adst[NN];
__device__ float g_x2[NN * CC];              // GAT output (relu'd) == v
__device__ float g_h450[HID];                // fc1 accumulator (zeroed by k_scan each call)
__device__ int   g_deg[NN];                  // zeroed by k_scan each call (after use)
__device__ int   g_rowptr[NN + 1];
__device__ int   g_pos[NN];
__device__ int   g_eid[NE];
__device__ int   g_ticket;                   // fc1 last-block ticket (reset by last block)

__device__ __forceinline__ float leaky(float v) { return v > 0.f ? v : 0.2f * v; }

// ---------------- CSR build (by dst) ----------------
__global__ void k_hist(const int* __restrict__ dst) {
    int e = blockIdx.x * blockDim.x + threadIdx.x;
    if (e < NE) atomicAdd(&g_deg[dst[e]], 1);
}

// exclusive scan of deg -> rowptr/pos; re-zero deg and h450 for this call
__global__ void k_scan() {
    const int CH = 10;
    int tid = threadIdx.x;
    int base = tid * CH;
    int local[CH];
    int s = 0;
#pragma unroll
    for (int k = 0; k < CH; k++) {
        int idx = base + k;
        int d = (idx < NN) ? g_deg[idx] : 0;
        local[k] = s;
        s += d;
    }
    int lane = tid & 31, wid = tid >> 5;
    int v = s;
#pragma unroll
    for (int o = 1; o < 32; o <<= 1) {
        int t = __shfl_up_sync(0xFFFFFFFFu, v, o);
        if (lane >= o) v += t;
    }
    __shared__ int ws[32];
    if (lane == 31) ws[wid] = v;
    __syncthreads();
    if (wid == 0) {
        int u = ws[lane];
#pragma unroll
        for (int o = 1; o < 32; o <<= 1) {
            int t = __shfl_up_sync(0xFFFFFFFFu, u, o);
            if (lane >= o) u += t;
        }
        ws[lane] = u;
    }
    __syncthreads();
    int excl = v - s + (wid > 0 ? ws[wid - 1] : 0);
#pragma unroll
    for (int k = 0; k < CH; k++) {
        int idx = base + k;
        if (idx <= NN) {
            int val = excl + local[k];
            g_rowptr[idx] = val;
            if (idx < NN) g_pos[idx] = val;
        }
    }
    __syncthreads();
    for (int i = tid; i < NN; i += 1024) g_deg[i] = 0;
    if (tid < HID) g_h450[tid] = 0.f;
}

__global__ void k_scatter(const int* __restrict__ dst) {
    int e = blockIdx.x * blockDim.x + threadIdx.x;
    if (e < NE) {
        int p = atomicAdd(&g_pos[dst[e]], 1);
        g_eid[p] = e;
    }
}

// ---------------- fused per-edge MLP + rank-1 outer-product reduce by dst ----------------
__global__ void k_edgeagg(const int* __restrict__ src, const float* __restrict__ x,
                          const float* __restrict__ ea, const float* __restrict__ w1,
                          const float* __restrict__ b1) {
    int gwarp = (blockIdx.x * blockDim.x + threadIdx.x) >> 5;
    int lane = threadIdx.x & 31;
    if (gwarp >= NN) return;
    int n = gwarp;

    float w1a = w1[lane], w1b = w1[MLPH + lane], b1v = b1[lane];

    float a0 = 0.f, a1 = 0.f, a2 = 0.f, a3 = 0.f, a4 = 0.f;
    float s0 = 0.f, s1 = 0.f, s2 = 0.f, s3 = 0.f, s4 = 0.f;

    int beg = g_rowptr[n], end = g_rowptr[n + 1];
    for (int j0 = beg; j0 < end; j0 += 32) {
        int j = j0 + lane;
        float ax = 0.f, ay = 0.f, x0 = 0.f, x1v = 0.f, x2v = 0.f, x3v = 0.f, x4v = 0.f;
        if (j < end) {
            int e = g_eid[j];
            int sN = src[e];
            float2 eav = ((const float2*)ea)[e];
            ax = eav.x; ay = eav.y;
            const float* xp = x + sN * FIN5;
            x0 = xp[0]; x1v = xp[1]; x2v = xp[2]; x3v = xp[3]; x4v = xp[4];
        }
        s0 += x0; s1 += x1v; s2 += x2v; s3 += x3v; s4 += x4v;
        int cnt = min(32, end - j0);
        for (int t = 0; t < cnt; t++) {
            float tax = __shfl_sync(0xFFFFFFFFu, ax, t);
            float tay = __shfl_sync(0xFFFFFFFFu, ay, t);
            float h = fmaxf(fmaf(tax, w1a, fmaf(tay, w1b, b1v)), 0.f);
            a0 = fmaf(h, __shfl_sync(0xFFFFFFFFu, x0,  t), a0);
            a1 = fmaf(h, __shfl_sync(0xFFFFFFFFu, x1v, t), a1);
            a2 = fmaf(h, __shfl_sync(0xFFFFFFFFu, x2v, t), a2);
            a3 = fmaf(h, __shfl_sync(0xFFFFFFFFu, x3v, t), a3);
            a4 = fmaf(h, __shfl_sync(0xFFFFFFFFu, x4v, t), a4);
        }
    }

    float* p = &g_pn[(size_t)n * 160];
    p[0 * 32 + lane] = a0;
    p[1 * 32 + lane] = a1;
    p[2 * 32 + lane] = a2;
    p[3 * 32 + lane] = a3;
    p[4 * 32 + lane] = a4;

#pragma unroll
    for (int o = 16; o > 0; o >>= 1) {
        s0 += __shfl_xor_sync(0xFFFFFFFFu, s0, o);
        s1 += __shfl_xor_sync(0xFFFFFFFFu, s1, o);
        s2 += __shfl_xor_sync(0xFFFFFFFFu, s2, o);
        s3 += __shfl_xor_sync(0xFFFFFFFFu, s3, o);
        s4 += __shfl_xor_sync(0xFFFFFFFFu, s4, o);
    }
    if (lane == 0) {
        float* sx = &g_sx[n * FIN5];
        sx[0] = s0; sx[1] = s1; sx[2] = s2; sx[3] = s3; sx[4] = s4;
    }
}

// ---- fused: x1 = relu(Pn@W2 + Sx@b2 + x@root + bias); xl = x1@gat_w; a_src/a_dst ----
__global__ void __launch_bounds__(1024) k_x1gat(const float* __restrict__ x,
                                                const float* __restrict__ w2,
                                                const float* __restrict__ b2,
                                                const float* __restrict__ nr,
                                                const float* __restrict__ nb,
                                                const float* __restrict__ gw,
                                                const float* __restrict__ att_s,
                                                const float* __restrict__ att_d) {
    __shared__ __align__(16) float w2s[MLPH * FIN5 * FOUT];   // 40 KB
    __shared__ float b2s[FIN5 * FOUT];
    __shared__ float nrs[FIN5 * FOUT];
    __shared__ float nbs[FOUT];
    __shared__ float gws[FOUT * CC];
    __shared__ float as_s[CC], ad_s[CC];
    int tid = threadIdx.x;
    for (int i = tid; i < MLPH * FIN5 * FOUT; i += 1024) w2s[i] = w2[i];
    if (tid < FIN5 * FOUT) { b2s[tid] = b2[tid]; nrs[tid] = nr[tid]; }
    if (tid < FOUT) nbs[tid] = nb[tid];
    for (int i = tid; i < FOUT * CC; i += 1024) gws[i] = gw[i];
    if (tid < CC) { as_s[tid] = att_s[tid]; ad_s[tid] = att_d[tid]; }
    __syncthreads();

    int gwarp = (blockIdx.x * 1024 + tid) >> 5;
    int lane = tid & 31;
    if (gwarp >= NN) return;
    int n = gwarp;

    const float* p = &g_pn[(size_t)n * 160];
    float p0 = p[0 * 32 + lane], p1 = p[1 * 32 + lane], p2 = p[2 * 32 + lane],
          p3 = p[3 * 32 + lane], p4 = p[4 * 32 + lane];

    float acc0 = nbs[lane], acc1 = nbs[32 + lane];
#pragma unroll
    for (int i = 0; i < FIN5; i++) {
        float xv = __ldg(&x[n * FIN5 + i]);
        float sxv = g_sx[n * FIN5 + i];
        acc0 = fmaf(xv, nrs[i * FOUT + lane], acc0);
        acc1 = fmaf(xv, nrs[i * FOUT + 32 + lane], acc1);
        acc0 = fmaf(sxv, b2s[i * FOUT + lane], acc0);
        acc1 = fmaf(sxv, b2s[i * FOUT + 32 + lane], acc1);
    }
#pragma unroll 4
    for (int m = 0; m < MLPH; m++) {
        float v0 = __shfl_sync(0xFFFFFFFFu, p0, m);
        float v1 = __shfl_sync(0xFFFFFFFFu, p1, m);
        float v2 = __shfl_sync(0xFFFFFFFFu, p2, m);
        float v3 = __shfl_sync(0xFFFFFFFFu, p3, m);
        float v4 = __shfl_sync(0xFFFFFFFFu, p4, m);
        const float* wrow = &w2s[m * (FIN5 * FOUT)];
        acc0 = fmaf(v0, wrow[0 * FOUT + lane], acc0);
        acc1 = fmaf(v0, wrow[0 * FOUT + 32 + lane], acc1);
        acc0 = fmaf(v1, wrow[1 * FOUT + lane], acc0);
        acc1 = fmaf(v1, wrow[1 * FOUT + 32 + lane], acc1);
        acc0 = fmaf(v2, wrow[2 * FOUT + lane], acc0);
        acc1 = fmaf(v2, wrow[2 * FOUT + 32 + lane], acc1);
        acc0 = fmaf(v3, wrow[3 * FOUT + lane], acc0);
        acc1 = fmaf(v3, wrow[3 * FOUT + 32 + lane], acc1);
        acc0 = fmaf(v4, wrow[4 * FOUT + lane], acc0);
        acc1 = fmaf(v4, wrow[4 * FOUT + 32 + lane], acc1);
    }
    float x1a = fmaxf(acc0, 0.f);
    float x1b = fmaxf(acc1, 0.f);

    float xv = 0.f;
#pragma unroll 8
    for (int k = 0; k < 32; k++) {
        float va = __shfl_sync(0xFFFFFFFFu, x1a, k);
        float vb = __shfl_sync(0xFFFFFFFFu, x1b, k);
        xv = fmaf(va, gws[k * CC + lane % CC], xv);
        xv = fmaf(vb, gws[(32 + k) * CC + lane % CC], xv);
    }
    if (lane < CC) g_xl[n * CC + lane] = xv;

    float vs = (lane < CC) ? xv * as_s[lane] : 0.f;
    float vd = (lane < CC) ? xv * ad_s[lane] : 0.f;
#pragma unroll
    for (int o = 16; o > 0; o >>= 1) {
        vs += __shfl_down_sync(0xFFFFFFFFu, vs, o);
        vd += __shfl_down_sync(0xFFFFFFFFu, vd, o);
    }
    if (lane == 0) { g_asrc[n] = vs; g_adst[n] = vd; }
}

// -------- GAT softmax-aggregate, single pass (no max shift; logits bounded) --------
__global__ void k_gat(const int* __restrict__ src, const float* __restrict__ gbias) {
    __shared__ float bias_s[CC];
    int tid = threadIdx.x;
    if (tid < CC) bias_s[tid] = gbias[tid];
    __syncthreads();

    int gwarp = (blockIdx.x * blockDim.x + tid) >> 5;
    int lane = tid & 31;
    if (gwarp >= NN) return;
    int n = gwarp;
    float asn = g_asrc[n], adn = g_adst[n];
    int beg = g_rowptr[n], end = g_rowptr[n + 1];

    float w0 = __expf(leaky(asn + adn));                  // self loop
    float denom = (lane == 0) ? w0 : 0.f;
    float acc = (lane < CC) ? w0 * g_xl[n * CC + lane] : 0.f;
    for (int j0 = beg; j0 < end; j0 += 32) {
        int j = j0 + lane;
        int s = 0;
        float w = 0.f;
        if (j < end) {
            int e = g_eid[j];
            s = src[e];
            w = __expf(leaky(g_asrc[s] + adn));
        }
        denom += w;
        int cnt = min(32, end - j0);
        for (int t = 0; t < cnt; t++) {
            float wt = __shfl_sync(0xFFFFFFFFu, w, t);
            int st = __shfl_sync(0xFFFFFFFFu, s, t);
            if (lane < CC) acc = fmaf(wt, g_xl[st * CC + lane], acc);
        }
    }
#pragma unroll
    for (int o = 16; o > 0; o >>= 1) denom += __shfl_xor_sync(0xFFFFFFFFu, denom, o);
    if (lane < CC) g_x2[n * CC + lane] = fmaxf(acc / denom + bias_s[lane], 0.f);
}

// -------- fc1 (in-block zero compaction, 8-chain ILP) + fused fc2 via last-block --------
#define F1_ROWS 512
#define F1_GRID ((NN * CC + F1_ROWS - 1) / F1_ROWS)
__global__ void __launch_bounds__(512) k_fc1(const float* __restrict__ W,
                                             const float* __restrict__ fc1b,
                                             const float* __restrict__ W2,
                                             const float* __restrict__ b2,
                                             float* __restrict__ out) {
    __shared__ float sv[F1_ROWS];
    __shared__ int   sr[F1_ROWS];
    __shared__ int   wcnt[16];
    __shared__ int   woff[16];
    __shared__ int   sm_m;
    const int TOT = NN * CC;
    int tid = threadIdx.x;
    int lane = tid & 31, wid = tid >> 5;
    int r0 = blockIdx.x * F1_ROWS;

    // in-block compaction of this block's 512 v values
    int r = r0 + tid;
    float val = (r < TOT) ? g_x2[r] : 0.f;
    bool nz = (val > 0.f);
    unsigned m = __ballot_sync(0xFFFFFFFFu, nz);
    if (lane == 0) wcnt[wid] = __popc(m);
    __syncthreads();
    if (wid == 0 && lane < 16) {
        int c = wcnt[lane];
        int pv = c;
#pragma unroll
        for (int o = 1; o < 16; o <<= 1) {
            int t2 = __shfl_up_sync(0xFFFFu, pv, o);
            if (lane >= o) pv += t2;
        }
        woff[lane] = pv - c;
        if (lane == 15) sm_m = pv;
    }
    __syncthreads();
    if (nz) {
        int p = woff[wid] + __popc(m & ((1u << lane) - 1u));
        sv[p] = val;
        sr[p] = r;
    }
    __syncthreads();
    int mtot = sm_m;

    // dense loop over compacted rows, 8 independent chains
    float a0 = 0.f, a1 = 0.f, a2 = 0.f, a3 = 0.f, a4 = 0.f, a5 = 0.f, a6 = 0.f, a7 = 0.f;
    if (tid < HID) {
        int k = 0;
        for (; k + 8 <= mtot; k += 8) {
            a0 = fmaf(sv[k],     W[(size_t)sr[k]     * HID + tid], a0);
            a1 = fmaf(sv[k + 1], W[(size_t)sr[k + 1] * HID + tid], a1);
            a2 = fmaf(sv[k + 2], W[(size_t)sr[k + 2] * HID + tid], a2);
            a3 = fmaf(sv[k + 3], W[(size_t)sr[k + 3] * HID + tid], a3);
            a4 = fmaf(sv[k + 4], W[(size_t)sr[k + 4] * HID + tid], a4);
            a5 = fmaf(sv[k + 5], W[(size_t)sr[k + 5] * HID + tid], a5);
            a6 = fmaf(sv[k + 6], W[(size_t)sr[k + 6] * HID + tid], a6);
            a7 = fmaf(sv[k + 7], W[(size_t)sr[k + 7] * HID + tid], a7);
        }
        for (; k < mtot; k++) a0 = fmaf(sv[k], W[(size_t)sr[k] * HID + tid], a0);
        float tot = ((a0 + a1) + (a2 + a3)) + ((a4 + a5) + (a6 + a7));
        if (tot != 0.f) atomicAdd(&g_h450[tid], tot);
    }

    // last-block does fc2
    __threadfence();
    __shared__ int s_last;
    __syncthreads();
    if (tid == 0) s_last = (atomicAdd(&g_ticket, 1) == F1_GRID - 1) ? 1 : 0;
    __syncthreads();
    if (!s_last) return;
    if (tid == 0) g_ticket = 0;

    __shared__ float hs[HID];
    __shared__ float part[4][FDIM];
    if (tid < HID) hs[tid] = fmaxf(g_h450[tid] + fc1b[tid], 0.f);
    __syncthreads();
    int grp = tid >> 7;          // 0..3
    int t = tid & 127;
    int j0 = grp * 113;
    int j1 = min(j0 + 113, HID);
    float acc = 0.f;
    for (int j = j0; j < j1; j++) acc = fmaf(hs[j], W2[j * FDIM + t], acc);
    part[grp][t] = acc;
    __syncthreads();
    if (tid < FDIM) {
        float v = ((part[0][tid] + part[1][tid]) + (part[2][tid] + part[3][tid])) + b2[tid];
        out[tid] = fmaxf(v, 0.f);
    }
}

// ---------------- launch ----------------
extern "C" void kernel_launch(void* const* d_in, const int* in_sizes, int n_in,
                              void* d_out, int out_size) {
    const float* x       = (const float*)d_in[0];
    const int*   eidx    = (const int*)d_in[1];
    const float* eattr   = (const float*)d_in[2];
    const float* mlp_w1  = (const float*)d_in[3];
    const float* mlp_b1  = (const float*)d_in[4];
    const float* mlp_w2  = (const float*)d_in[5];
    const float* mlp_b2  = (const float*)d_in[6];
    const float* nn_root = (const float*)d_in[7];
    const float* nn_bias = (const float*)d_in[8];
    const float* gat_w   = (const float*)d_in[9];
    const float* att_src = (const float*)d_in[10];
    const float* att_dst = (const float*)d_in[11];
    const float* gat_b   = (const float*)d_in[12];
    const float* fc1_w   = (const float*)d_in[13];
    const float* fc1_b   = (const float*)d_in[14];
    const float* fc2_w   = (const float*)d_in[15];
    const float* fc2_b   = (const float*)d_in[16];
    float* out = (float*)d_out;

    const int* src = eidx;          // edge_index[0]
    const int* dst = eidx + NE;     // edge_index[1]

    k_hist<<<(NE + 255) / 256, 256>>>(dst);
    k_scan<<<1, 1024>>>();
    k_scatter<<<(NE + 255) / 256, 256>>>(dst);
    k_edgeagg<<<(NN * 32 + 255) / 256, 256>>>(src, x, eattr, mlp_w1, mlp_b1);
    k_x1gat<<<(NN * 32 + 1023) / 1024, 1024>>>(x, mlp_w2, mlp_b2, nn_root, nn_bias,
                                               gat_w, att_src, att_dst);
    k_gat<<<(NN * 32 + 255) / 256, 256>>>(src, gat_b);
    k_fc1<<<F1_GRID, 512>>>(fc1_w, fc1_b, fc2_w, fc2_b, out);
}

// round 11
// speedup vs baseline: 3.0212x; 1.0479x over previous
#include <cuda_runtime.h>
#include <cstdint>
#include <cstddef>

#define NN   10000
#define NE   320000
#define FIN5 5
#define FOUT 64
#define CC   27
#define MLPH 32
#define HID  450
#define FDIM 128

// ---------------- scratch (static device globals; no allocation) ----------------
__device__ float g_pn[(size_t)NN * 160];
__device__ float g_sx[NN * FIN5];
__device__ float g_xl[NN * CC];
__device__ float g_asrc[NN];
__device__ float g_adst[NN];
__device__ float g_x2[NN * CC];
__device__ float g_h450[HID];
__device__ int   g_deg[NN];
__device__ int   g_rowptr[NN + 1];
__device__ int   g_pos[NN];
__device__ int   g_eid[NE];
__device__ int   g_tick1;                    // hist->scan ticket
__device__ int   g_tick2;                    // fc1->fc2 ticket

__device__ __forceinline__ float leaky(float v) { return v > 0.f ? v : 0.2f * v; }

// ---------------- hist (4 edges/thread, ILP) + fused scan in last block ----------------
#define H_BLK  1024
#define H_PER  4
#define H_GRID ((NE + H_BLK * H_PER - 1) / (H_BLK * H_PER))
__global__ void __launch_bounds__(1024) k_hist(const int* __restrict__ dst) {
    int base = (blockIdx.x * H_BLK + threadIdx.x) * H_PER;
    if (base + H_PER <= NE) {
        int4 d = *(const int4*)&dst[base];
        atomicAdd(&g_deg[d.x], 1);
        atomicAdd(&g_deg[d.y], 1);
        atomicAdd(&g_deg[d.z], 1);
        atomicAdd(&g_deg[d.w], 1);
    } else {
        for (int k = 0; k < H_PER; k++) {
            int i = base + k;
            if (i < NE) atomicAdd(&g_deg[dst[i]], 1);
        }
    }
    __threadfence();
    __shared__ int s_last;
    __syncthreads();
    if (threadIdx.x == 0) s_last = (atomicAdd(&g_tick1, 1) == H_GRID - 1) ? 1 : 0;
    __syncthreads();
    if (!s_last) return;
    if (threadIdx.x == 0) g_tick1 = 0;
    __threadfence();

    // ---- scan (1024 threads, 10/thread) ----
    const int CH = 10;
    int tid = threadIdx.x;
    int sb = tid * CH;
    int local[CH];
    int s = 0;
#pragma unroll
    for (int k = 0; k < CH; k++) {
        int idx = sb + k;
        int d = (idx < NN) ? g_deg[idx] : 0;
        local[k] = s;
        s += d;
    }
    int lane = tid & 31, wid = tid >> 5;
    int v = s;
#pragma unroll
    for (int o = 1; o < 32; o <<= 1) {
        int t = __shfl_up_sync(0xFFFFFFFFu, v, o);
        if (lane >= o) v += t;
    }
    __shared__ int ws[32];
    if (lane == 31) ws[wid] = v;
    __syncthreads();
    if (wid == 0) {
        int u = ws[lane];
#pragma unroll
        for (int o = 1; o < 32; o <<= 1) {
            int t = __shfl_up_sync(0xFFFFFFFFu, u, o);
            if (lane >= o) u += t;
        }
        ws[lane] = u;
    }
    __syncthreads();
    int excl = v - s + (wid > 0 ? ws[wid - 1] : 0);
#pragma unroll
    for (int k = 0; k < CH; k++) {
        int idx = sb + k;
        if (idx <= NN) {
            int val = excl + local[k];
            g_rowptr[idx] = val;
            if (idx < NN) g_pos[idx] = val;
        }
    }
    __syncthreads();
    for (int i = tid; i < NN; i += 1024) g_deg[i] = 0;
    if (tid < HID) g_h450[tid] = 0.f;
}

// ---------------- scatter (4 edges/thread, overlapped atomics) ----------------
__global__ void k_scatter(const int* __restrict__ dst) {
    int base = (blockIdx.x * blockDim.x + threadIdx.x) * 4;
    if (base + 4 <= NE) {
        int4 d = *(const int4*)&dst[base];
        int p0 = atomicAdd(&g_pos[d.x], 1);
        int p1 = atomicAdd(&g_pos[d.y], 1);
        int p2 = atomicAdd(&g_pos[d.z], 1);
        int p3 = atomicAdd(&g_pos[d.w], 1);
        g_eid[p0] = base;
        g_eid[p1] = base + 1;
        g_eid[p2] = base + 2;
        g_eid[p3] = base + 3;
    } else {
        for (int k = 0; k < 4; k++) {
            int i = base + k;
            if (i < NE) {
                int p = atomicAdd(&g_pos[dst[i]], 1);
                g_eid[p] = i;
            }
        }
    }
}

// ------- per-edge MLP + rank-1 reduce; smem record staging (2 MIO/edge) -------
__global__ void __launch_bounds__(256) k_edgeagg(const int* __restrict__ src,
                                                 const float* __restrict__ x,
                                                 const float* __restrict__ ea,
                                                 const float* __restrict__ w1,
                                                 const float* __restrict__ b1) {
    __shared__ __align__(16) float srec[8][32][8];   // 8 KB
    int tid = threadIdx.x;
    int wid = tid >> 5, lane = tid & 31;
    int n = (blockIdx.x * 256 + tid) >> 5;
    if (n >= NN) return;

    float w1a = w1[lane], w1b = w1[MLPH + lane], b1v = b1[lane];

    float a0 = 0.f, a1 = 0.f, a2 = 0.f, a3 = 0.f, a4 = 0.f;
    float s0 = 0.f, s1 = 0.f, s2 = 0.f, s3 = 0.f, s4 = 0.f;

    int beg = g_rowptr[n], end = g_rowptr[n + 1];
    for (int j0 = beg; j0 < end; j0 += 32) {
        int j = j0 + lane;
        float ax = 0.f, ay = 0.f, x0 = 0.f, x1v = 0.f, x2v = 0.f, x3v = 0.f, x4v = 0.f;
        if (j < end) {
            int e = g_eid[j];
            int sN = src[e];
            float2 eav = ((const float2*)ea)[e];
            ax = eav.x; ay = eav.y;
            const float* xp = x + sN * FIN5;
            x0 = xp[0]; x1v = xp[1]; x2v = xp[2]; x3v = xp[3]; x4v = xp[4];
        }
        s0 += x0; s1 += x1v; s2 += x2v; s3 += x3v; s4 += x4v;
        float4* rp = (float4*)&srec[wid][lane][0];
        rp[0] = make_float4(ax, ay, x0, x1v);
        rp[1] = make_float4(x2v, x3v, x4v, 0.f);
        __syncwarp();
        int cnt = min(32, end - j0);
        for (int t = 0; t < cnt; t++) {
            const float4* qp = (const float4*)&srec[wid][t][0];
            float4 q0 = qp[0];
            float4 q1 = qp[1];
            float h = fmaxf(fmaf(q0.x, w1a, fmaf(q0.y, w1b, b1v)), 0.f);
            a0 = fmaf(h, q0.z, a0);
            a1 = fmaf(h, q0.w, a1);
            a2 = fmaf(h, q1.x, a2);
            a3 = fmaf(h, q1.y, a3);
            a4 = fmaf(h, q1.z, a4);
        }
        __syncwarp();
    }

    float* p = &g_pn[(size_t)n * 160];
    p[0 * 32 + lane] = a0;
    p[1 * 32 + lane] = a1;
    p[2 * 32 + lane] = a2;
    p[3 * 32 + lane] = a3;
    p[4 * 32 + lane] = a4;

#pragma unroll
    for (int o = 16; o > 0; o >>= 1) {
        s0 += __shfl_xor_sync(0xFFFFFFFFu, s0, o);
        s1 += __shfl_xor_sync(0xFFFFFFFFu, s1, o);
        s2 += __shfl_xor_sync(0xFFFFFFFFu, s2, o);
        s3 += __shfl_xor_sync(0xFFFFFFFFu, s3, o);
        s4 += __shfl_xor_sync(0xFFFFFFFFu, s4, o);
    }
    if (lane == 0) {
        float* sx = &g_sx[n * FIN5];
        sx[0] = s0; sx[1] = s1; sx[2] = s2; sx[3] = s3; sx[4] = s4;
    }
}

// ---- fused: x1 = relu(Pn@W2 + Sx@b2 + x@root + bias); xl = x1@gat_w; a_src/a_dst ----
__global__ void __launch_bounds__(1024) k_x1gat(const float* __restrict__ x,
                                                const float* __restrict__ w2,
                                                const float* __restrict__ b2,
                                                const float* __restrict__ nr,
                                                const float* __restrict__ nb,
                                                const float* __restrict__ gw,
                                                const float* __restrict__ att_s,
                                                const float* __restrict__ att_d) {
    __shared__ __align__(16) float w2s[MLPH * FIN5 * FOUT];   // 40 KB
    __shared__ float b2s[FIN5 * FOUT];
    __shared__ float nrs[FIN5 * FOUT];
    __shared__ float nbs[FOUT];
    __shared__ float gws[FOUT * CC];
    __shared__ float as_s[CC], ad_s[CC];
    int tid = threadIdx.x;
    for (int i = tid; i < MLPH * FIN5 * FOUT; i += 1024) w2s[i] = w2[i];
    if (tid < FIN5 * FOUT) { b2s[tid] = b2[tid]; nrs[tid] = nr[tid]; }
    if (tid < FOUT) nbs[tid] = nb[tid];
    for (int i = tid; i < FOUT * CC; i += 1024) gws[i] = gw[i];
    if (tid < CC) { as_s[tid] = att_s[tid]; ad_s[tid] = att_d[tid]; }
    __syncthreads();

    int gwarp = (blockIdx.x * 1024 + tid) >> 5;
    int lane = tid & 31;
    if (gwarp >= NN) return;
    int n = gwarp;

    const float* p = &g_pn[(size_t)n * 160];
    float p0 = p[0 * 32 + lane], p1 = p[1 * 32 + lane], p2 = p[2 * 32 + lane],
          p3 = p[3 * 32 + lane], p4 = p[4 * 32 + lane];

    float acc0 = nbs[lane], acc1 = nbs[32 + lane];
#pragma unroll
    for (int i = 0; i < FIN5; i++) {
        float xv = __ldg(&x[n * FIN5 + i]);
        float sxv = g_sx[n * FIN5 + i];
        acc0 = fmaf(xv, nrs[i * FOUT + lane], acc0);
        acc1 = fmaf(xv, nrs[i * FOUT + 32 + lane], acc1);
        acc0 = fmaf(sxv, b2s[i * FOUT + lane], acc0);
        acc1 = fmaf(sxv, b2s[i * FOUT + 32 + lane], acc1);
    }
#pragma unroll 4
    for (int m = 0; m < MLPH; m++) {
        float v0 = __shfl_sync(0xFFFFFFFFu, p0, m);
        float v1 = __shfl_sync(0xFFFFFFFFu, p1, m);
        float v2 = __shfl_sync(0xFFFFFFFFu, p2, m);
        float v3 = __shfl_sync(0xFFFFFFFFu, p3, m);
        float v4 = __shfl_sync(0xFFFFFFFFu, p4, m);
        const float* wrow = &w2s[m * (FIN5 * FOUT)];
        acc0 = fmaf(v0, wrow[0 * FOUT + lane], acc0);
        acc1 = fmaf(v0, wrow[0 * FOUT + 32 + lane], acc1);
        acc0 = fmaf(v1, wrow[1 * FOUT + lane], acc0);
        acc1 = fmaf(v1, wrow[1 * FOUT + 32 + lane], acc1);
        acc0 = fmaf(v2, wrow[2 * FOUT + lane], acc0);
        acc1 = fmaf(v2, wrow[2 * FOUT + 32 + lane], acc1);
        acc0 = fmaf(v3, wrow[3 * FOUT + lane], acc0);
        acc1 = fmaf(v3, wrow[3 * FOUT + 32 + lane], acc1);
        acc0 = fmaf(v4, wrow[4 * FOUT + lane], acc0);
        acc1 = fmaf(v4, wrow[4 * FOUT + 32 + lane], acc1);
    }
    float x1a = fmaxf(acc0, 0.f);
    float x1b = fmaxf(acc1, 0.f);

    float xv = 0.f;
#pragma unroll 8
    for (int k = 0; k < 32; k++) {
        float va = __shfl_sync(0xFFFFFFFFu, x1a, k);
        float vb = __shfl_sync(0xFFFFFFFFu, x1b, k);
        xv = fmaf(va, gws[k * CC + lane % CC], xv);
        xv = fmaf(vb, gws[(32 + k) * CC + lane % CC], xv);
    }
    if (lane < CC) g_xl[n * CC + lane] = xv;

    float vs = (lane < CC) ? xv * as_s[lane] : 0.f;
    float vd = (lane < CC) ? xv * ad_s[lane] : 0.f;
#pragma unroll
    for (int o = 16; o > 0; o >>= 1) {
        vs += __shfl_down_sync(0xFFFFFFFFu, vs, o);
        vd += __shfl_down_sync(0xFFFFFFFFu, vd, o);
    }
    if (lane == 0) { g_asrc[n] = vs; g_adst[n] = vd; }
}

// -------- GAT softmax-aggregate, single pass, smem (w,s) staging --------
__global__ void __launch_bounds__(256) k_gat(const int* __restrict__ src,
                                             const float* __restrict__ gbias) {
    __shared__ float bias_s[CC];
    __shared__ __align__(8) float2 sws[8][32];       // 2 KB
    int tid = threadIdx.x;
    if (tid < CC) bias_s[tid] = gbias[tid];
    __syncthreads();

    int wid = tid >> 5, lane = tid & 31;
    int n = (blockIdx.x * 256 + tid) >> 5;
    if (n >= NN) return;
    float asn = g_asrc[n], adn = g_adst[n];
    int beg = g_rowptr[n], end = g_rowptr[n + 1];

    float w0 = __expf(leaky(asn + adn));              // self loop
    float denom = (lane == 0) ? w0 : 0.f;
    float acc = (lane < CC) ? w0 * g_xl[n * CC + lane] : 0.f;
    for (int j0 = beg; j0 < end; j0 += 32) {
        int j = j0 + lane;
        int s = 0;
        float w = 0.f;
        if (j < end) {
            int e = g_eid[j];
            s = src[e];
            w = __expf(leaky(g_asrc[s] + adn));
        }
        denom += w;
        sws[wid][lane] = make_float2(w, __int_as_float(s));
        __syncwarp();
        int cnt = min(32, end - j0);
        for (int t = 0; t < cnt; t++) {
            float2 q = sws[wid][t];
            float wt = q.x;
            int st = __float_as_int(q.y);
            if (lane < CC) acc = fmaf(wt, g_xl[st * CC + lane], acc);
        }
        __syncwarp();
    }
#pragma unroll
    for (int o = 16; o > 0; o >>= 1) denom += __shfl_xor_sync(0xFFFFFFFFu, denom, o);
    if (lane < CC) g_x2[n * CC + lane] = fmaxf(acc / denom + bias_s[lane], 0.f);
}

// -------- fc1 (in-block zero compaction, 8-chain ILP) + fused fc2 via last-block --------
#define F1_ROWS 512
#define F1_GRID ((NN * CC + F1_ROWS - 1) / F1_ROWS)
__global__ void __launch_bounds__(512) k_fc1(const float* __restrict__ W,
                                             const float* __restrict__ fc1b,
                                             const float* __restrict__ W2,
                                             const float* __restrict__ b2,
                                             float* __restrict__ out) {
    __shared__ float sv[F1_ROWS];
    __shared__ int   sr[F1_ROWS];
    __shared__ int   wcnt[16];
    __shared__ int   woff[16];
    __shared__ int   sm_m;
    const int TOT = NN * CC;
    int tid = threadIdx.x;
    int lane = tid & 31, wid = tid >> 5;
    int r0 = blockIdx.x * F1_ROWS;

    int r = r0 + tid;
    float val = (r < TOT) ? g_x2[r] : 0.f;
    bool nz = (val > 0.f);
    unsigned m = __ballot_sync(0xFFFFFFFFu, nz);
    if (lane == 0) wcnt[wid] = __popc(m);
    __syncthreads();
    if (wid == 0 && lane < 16) {
        int c = wcnt[lane];
        int pv = c;
#pragma unroll
        for (int o = 1; o < 16; o <<= 1) {
            int t2 = __shfl_up_sync(0xFFFFu, pv, o);
            if (lane >= o) pv += t2;
        }
        woff[lane] = pv - c;
        if (lane == 15) sm_m = pv;
    }
    __syncthreads();
    if (nz) {
        int p = woff[wid] + __popc(m & ((1u << lane) - 1u));
        sv[p] = val;
        sr[p] = r;
    }
    __syncthreads();
    int mtot = sm_m;

    float a0 = 0.f, a1 = 0.f, a2 = 0.f, a3 = 0.f, a4 = 0.f, a5 = 0.f, a6 = 0.f, a7 = 0.f;
    if (tid < HID) {
        int k = 0;
        for (; k + 8 <= mtot; k += 8) {
            a0 = fmaf(sv[k],     W[(size_t)sr[k]     * HID + tid], a0);
            a1 = fmaf(sv[k + 1], W[(size_t)sr[k + 1] * HID + tid], a1);
            a2 = fmaf(sv[k + 2], W[(size_t)sr[k + 2] * HID + tid], a2);
            a3 = fmaf(sv[k + 3], W[(size_t)sr[k + 3] * HID + tid], a3);
            a4 = fmaf(sv[k + 4], W[(size_t)sr[k + 4] * HID + tid], a4);
            a5 = fmaf(sv[k + 5], W[(size_t)sr[k + 5] * HID + tid], a5);
            a6 = fmaf(sv[k + 6], W[(size_t)sr[k + 6] * HID + tid], a6);
            a7 = fmaf(sv[k + 7], W[(size_t)sr[k + 7] * HID + tid], a7);
        }
        for (; k < mtot; k++) a0 = fmaf(sv[k], W[(size_t)sr[k] * HID + tid], a0);
        float tot = ((a0 + a1) + (a2 + a3)) + ((a4 + a5) + (a6 + a7));
        if (tot != 0.f) atomicAdd(&g_h450[tid], tot);
    }

    __threadfence();
    __shared__ int s_last;
    __syncthreads();
    if (tid == 0) s_last = (atomicAdd(&g_tick2, 1) == F1_GRID - 1) ? 1 : 0;
    __syncthreads();
    if (!s_last) return;
    if (tid == 0) g_tick2 = 0;

    __shared__ float hs[HID];
    __shared__ float part[4][FDIM];
    if (tid < HID) hs[tid] = fmaxf(g_h450[tid] + fc1b[tid], 0.f);
    __syncthreads();
    int grp = tid >> 7;          // 0..3
    int t = tid & 127;
    int j0 = grp * 113;
    int j1 = min(j0 + 113, HID);
    float acc = 0.f;
    for (int j = j0; j < j1; j++) acc = fmaf(hs[j], W2[j * FDIM + t], acc);
    part[grp][t] = acc;
    __syncthreads();
    if (tid < FDIM) {
        float v = ((part[0][tid] + part[1][tid]) + (part[2][tid] + part[3][tid])) + b2[tid];
        out[tid] = fmaxf(v, 0.f);
    }
}

// ---------------- launch ----------------
extern "C" void kernel_launch(void* const* d_in, const int* in_sizes, int n_in,
                              void* d_out, int out_size) {
    const float* x       = (const float*)d_in[0];
    const int*   eidx    = (const int*)d_in[1];
    const float* eattr   = (const float*)d_in[2];
    const float* mlp_w1  = (const float*)d_in[3];
    const float* mlp_b1  = (const float*)d_in[4];
    const float* mlp_w2  = (const float*)d_in[5];
    const float* mlp_b2  = (const float*)d_in[6];
    const float* nn_root = (const float*)d_in[7];
    const float* nn_bias = (const float*)d_in[8];
    const float* gat_w   = (const float*)d_in[9];
    const float* att_src = (const float*)d_in[10];
    const float* att_dst = (const float*)d_in[11];
    const float* gat_b   = (const float*)d_in[12];
    const float* fc1_w   = (const float*)d_in[13];
    const float* fc1_b   = (const float*)d_in[14];
    const float* fc2_w   = (const float*)d_in[15];
    const float* fc2_b   = (const float*)d_in[16];
    float* out = (float*)d_out;

    const int* src = eidx;          // edge_index[0]
    const int* dst = eidx + NE;     // edge_index[1]

    k_hist<<<H_GRID, H_BLK>>>(dst);                       // + fused scan (last block)
    k_scatter<<<(NE / 4 + 255) / 256, 256>>>(dst);
    k_edgeagg<<<(NN * 32 + 255) / 256, 256>>>(src, x, eattr, mlp_w1, mlp_b1);
    k_x1gat<<<(NN * 32 + 1023) / 1024, 1024>>>(x, mlp_w2, mlp_b2, nn_root, nn_bias,
                                               gat_w, att_src, att_dst);
    k_gat<<<(NN * 32 + 255) / 256, 256>>>(src, gat_b);
    k_fc1<<<F1_GRID, 512>>>(fc1_w, fc1_b, fc2_w, fc2_b, out);
}

// round 12
// speedup vs baseline: 3.2664x; 1.0812x over previous
#include <cuda_runtime.h>
#include <cstdint>
#include <cstddef>

#define NN   10000
#define NE   320000
#define FIN5 5
#define FOUT 64
#define CC   27
#define MLPH 32
#define HID  450
#define FDIM 128

// ---------------- scratch (static device globals; no allocation) ----------------
__device__ float g_pn[(size_t)NN * 160];
__device__ float g_sx[NN * FIN5];
__device__ float g_xl[NN * CC];
__device__ float g_asrc[NN];
__device__ float g_adst[NN];
__device__ float g_x2[NN * CC];
__device__ float g_h450[HID];
__device__ int   g_deg[NN];
__device__ int   g_rowptr[NN + 1];
__device__ int   g_pos[NN];
__device__ int   g_eid[NE];
__device__ int   g_tick1;                    // hist->scan ticket
__device__ int   g_tick2;                    // fc1->fc2 ticket

__device__ __forceinline__ float leaky(float v) { return v > 0.f ? v : 0.2f * v; }

// ---------------- hist (4 edges/thread, ILP) + fused scan in last block ----------------
#define H_BLK  1024
#define H_PER  4
#define H_GRID ((NE + H_BLK * H_PER - 1) / (H_BLK * H_PER))
__global__ void __launch_bounds__(1024) k_hist(const int* __restrict__ dst) {
    int base = (blockIdx.x * H_BLK + threadIdx.x) * H_PER;
    if (base + H_PER <= NE) {
        int4 d = *(const int4*)&dst[base];
        atomicAdd(&g_deg[d.x], 1);
        atomicAdd(&g_deg[d.y], 1);
        atomicAdd(&g_deg[d.z], 1);
        atomicAdd(&g_deg[d.w], 1);
    } else {
        for (int k = 0; k < H_PER; k++) {
            int i = base + k;
            if (i < NE) atomicAdd(&g_deg[dst[i]], 1);
        }
    }
    __threadfence();
    __shared__ int s_last;
    __syncthreads();
    if (threadIdx.x == 0) s_last = (atomicAdd(&g_tick1, 1) == H_GRID - 1) ? 1 : 0;
    __syncthreads();
    if (!s_last) return;
    if (threadIdx.x == 0) g_tick1 = 0;
    __threadfence();

    // ---- scan (1024 threads, 10/thread) ----
    const int CH = 10;
    int tid = threadIdx.x;
    int sb = tid * CH;
    int local[CH];
    int s = 0;
#pragma unroll
    for (int k = 0; k < CH; k++) {
        int idx = sb + k;
        int d = (idx < NN) ? g_deg[idx] : 0;
        local[k] = s;
        s += d;
    }
    int lane = tid & 31, wid = tid >> 5;
    int v = s;
#pragma unroll
    for (int o = 1; o < 32; o <<= 1) {
        int t = __shfl_up_sync(0xFFFFFFFFu, v, o);
        if (lane >= o) v += t;
    }
    __shared__ int ws[32];
    if (lane == 31) ws[wid] = v;
    __syncthreads();
    if (wid == 0) {
        int u = ws[lane];
#pragma unroll
        for (int o = 1; o < 32; o <<= 1) {
            int t = __shfl_up_sync(0xFFFFFFFFu, u, o);
            if (lane >= o) u += t;
        }
        ws[lane] = u;
    }
    __syncthreads();
    int excl = v - s + (wid > 0 ? ws[wid - 1] : 0);
#pragma unroll
    for (int k = 0; k < CH; k++) {
        int idx = sb + k;
        if (idx <= NN) {
            int val = excl + local[k];
            g_rowptr[idx] = val;
            if (idx < NN) g_pos[idx] = val;
        }
    }
    __syncthreads();
    for (int i = tid; i < NN; i += 1024) g_deg[i] = 0;
    if (tid < HID) g_h450[tid] = 0.f;
}

// ---------------- scatter (4 edges/thread, overlapped atomics) ----------------
__global__ void k_scatter(const int* __restrict__ dst) {
    int base = (blockIdx.x * blockDim.x + threadIdx.x) * 4;
    if (base + 4 <= NE) {
        int4 d = *(const int4*)&dst[base];
        int p0 = atomicAdd(&g_pos[d.x], 1);
        int p1 = atomicAdd(&g_pos[d.y], 1);
        int p2 = atomicAdd(&g_pos[d.z], 1);
        int p3 = atomicAdd(&g_pos[d.w], 1);
        g_eid[p0] = base;
        g_eid[p1] = base + 1;
        g_eid[p2] = base + 2;
        g_eid[p3] = base + 3;
    } else {
        for (int k = 0; k < 4; k++) {
            int i = base + k;
            if (i < NE) {
                int p = atomicAdd(&g_pos[dst[i]], 1);
                g_eid[p] = i;
            }
        }
    }
}

// ------- per-edge MLP + rank-1 reduce; smem record staging (2 MIO/edge) -------
__global__ void __launch_bounds__(256) k_edgeagg(const int* __restrict__ src,
                                                 const float* __restrict__ x,
                                                 const float* __restrict__ ea,
                                                 const float* __restrict__ w1,
                                                 const float* __restrict__ b1) {
    __shared__ __align__(16) float srec[8][32][8];   // 8 KB
    int tid = threadIdx.x;
    int wid = tid >> 5, lane = tid & 31;
    int n = (blockIdx.x * 256 + tid) >> 5;
    if (n >= NN) return;

    float w1a = w1[lane], w1b = w1[MLPH + lane], b1v = b1[lane];

    float a0 = 0.f, a1 = 0.f, a2 = 0.f, a3 = 0.f, a4 = 0.f;
    float s0 = 0.f, s1 = 0.f, s2 = 0.f, s3 = 0.f, s4 = 0.f;

    int beg = g_rowptr[n], end = g_rowptr[n + 1];
    for (int j0 = beg; j0 < end; j0 += 32) {
        int j = j0 + lane;
        float ax = 0.f, ay = 0.f, x0 = 0.f, x1v = 0.f, x2v = 0.f, x3v = 0.f, x4v = 0.f;
        if (j < end) {
            int e = g_eid[j];
            int sN = src[e];
            float2 eav = ((const float2*)ea)[e];
            ax = eav.x; ay = eav.y;
            const float* xp = x + sN * FIN5;
            x0 = xp[0]; x1v = xp[1]; x2v = xp[2]; x3v = xp[3]; x4v = xp[4];
        }
        s0 += x0; s1 += x1v; s2 += x2v; s3 += x3v; s4 += x4v;
        float4* rp = (float4*)&srec[wid][lane][0];
        rp[0] = make_float4(ax, ay, x0, x1v);
        rp[1] = make_float4(x2v, x3v, x4v, 0.f);
        __syncwarp();
        int cnt = min(32, end - j0);
        for (int t = 0; t < cnt; t++) {
            const float4* qp = (const float4*)&srec[wid][t][0];
            float4 q0 = qp[0];
            float4 q1 = qp[1];
            float h = fmaxf(fmaf(q0.x, w1a, fmaf(q0.y, w1b, b1v)), 0.f);
            a0 = fmaf(h, q0.z, a0);
            a1 = fmaf(h, q0.w, a1);
            a2 = fmaf(h, q1.x, a2);
            a3 = fmaf(h, q1.y, a3);
            a4 = fmaf(h, q1.z, a4);
        }
        __syncwarp();
    }

    float* p = &g_pn[(size_t)n * 160];
    p[0 * 32 + lane] = a0;
    p[1 * 32 + lane] = a1;
    p[2 * 32 + lane] = a2;
    p[3 * 32 + lane] = a3;
    p[4 * 32 + lane] = a4;

#pragma unroll
    for (int o = 16; o > 0; o >>= 1) {
        s0 += __shfl_xor_sync(0xFFFFFFFFu, s0, o);
        s1 += __shfl_xor_sync(0xFFFFFFFFu, s1, o);
        s2 += __shfl_xor_sync(0xFFFFFFFFu, s2, o);
        s3 += __shfl_xor_sync(0xFFFFFFFFu, s3, o);
        s4 += __shfl_xor_sync(0xFFFFFFFFu, s4, o);
    }
    if (lane == 0) {
        float* sx = &g_sx[n * FIN5];
        sx[0] = s0; sx[1] = s1; sx[2] = s2; sx[3] = s3; sx[4] = s4;
    }
}

// ---- fused x1/GAT-prep: 4 nodes per warp (amortized W2 LDS, 8 acc chains) ----
__global__ void __launch_bounds__(256) k_x1gat(const float* __restrict__ x,
                                               const float* __restrict__ w2,
                                               const float* __restrict__ b2,
                                               const float* __restrict__ nr,
                                               const float* __restrict__ nb,
                                               const float* __restrict__ gw,
                                               const float* __restrict__ att_s,
                                               const float* __restrict__ att_d) {
    __shared__ __align__(16) float w2s[MLPH * FIN5 * FOUT];   // 40 KB
    __shared__ float b2s[FIN5 * FOUT];
    __shared__ float nrs[FIN5 * FOUT];
    __shared__ float nbs[FOUT];
    __shared__ float gws[FOUT * CC];
    __shared__ float as_s[CC], ad_s[CC];
    int tid = threadIdx.x;
    for (int i = tid; i < MLPH * FIN5 * FOUT; i += 256) w2s[i] = w2[i];
    for (int i = tid; i < FIN5 * FOUT; i += 256) { b2s[i] = b2[i]; nrs[i] = nr[i]; }
    if (tid < FOUT) nbs[tid] = nb[tid];
    for (int i = tid; i < FOUT * CC; i += 256) gws[i] = gw[i];
    if (tid < CC) { as_s[tid] = att_s[tid]; ad_s[tid] = att_d[tid]; }
    __syncthreads();

    int wid = tid >> 5, lane = tid & 31;
    int nbase = (blockIdx.x * 8 + wid) * 4;
    if (nbase >= NN) return;

    // load Pn rows for 4 nodes (lane = m index)
    float p[FIN5][4];
#pragma unroll
    for (int nd = 0; nd < 4; nd++) {
        int n = min(nbase + nd, NN - 1);
        const float* pr = &g_pn[(size_t)n * 160];
#pragma unroll
        for (int i = 0; i < FIN5; i++) p[i][nd] = pr[i * 32 + lane];
    }

    float acc0[4], acc1[4];
#pragma unroll
    for (int nd = 0; nd < 4; nd++) { acc0[nd] = nbs[lane]; acc1[nd] = nbs[32 + lane]; }

#pragma unroll
    for (int nd = 0; nd < 4; nd++) {
        int n = min(nbase + nd, NN - 1);
#pragma unroll
        for (int i = 0; i < FIN5; i++) {
            float xv = __ldg(&x[n * FIN5 + i]);
            float sxv = g_sx[n * FIN5 + i];
            acc0[nd] = fmaf(xv, nrs[i * FOUT + lane], acc0[nd]);
            acc1[nd] = fmaf(xv, nrs[i * FOUT + 32 + lane], acc1[nd]);
            acc0[nd] = fmaf(sxv, b2s[i * FOUT + lane], acc0[nd]);
            acc1[nd] = fmaf(sxv, b2s[i * FOUT + 32 + lane], acc1[nd]);
        }
    }

    // main contraction: W2 LDS shared across 4 nodes, 8 accumulator chains
#pragma unroll 2
    for (int m = 0; m < MLPH; m++) {
        float w0_[FIN5], w1_[FIN5];
        const float* wrow = &w2s[m * (FIN5 * FOUT)];
#pragma unroll
        for (int i = 0; i < FIN5; i++) {
            w0_[i] = wrow[i * FOUT + lane];
            w1_[i] = wrow[i * FOUT + 32 + lane];
        }
#pragma unroll
        for (int nd = 0; nd < 4; nd++) {
#pragma unroll
            for (int i = 0; i < FIN5; i++) {
                float v = __shfl_sync(0xFFFFFFFFu, p[i][nd], m);
                acc0[nd] = fmaf(v, w0_[i], acc0[nd]);
                acc1[nd] = fmaf(v, w1_[i], acc1[nd]);
            }
        }
    }

    float x1a[4], x1b[4];
#pragma unroll
    for (int nd = 0; nd < 4; nd++) {
        x1a[nd] = fmaxf(acc0[nd], 0.f);
        x1b[nd] = fmaxf(acc1[nd], 0.f);
    }

    // xl = x1 @ gat_w ; gws LDS hoisted over 4 nodes
    int cidx = lane % CC;
    float xv4[4] = {0.f, 0.f, 0.f, 0.f};
#pragma unroll 4
    for (int k = 0; k < 32; k++) {
        float g0 = gws[k * CC + cidx];
        float g1 = gws[(32 + k) * CC + cidx];
#pragma unroll
        for (int nd = 0; nd < 4; nd++) {
            float va = __shfl_sync(0xFFFFFFFFu, x1a[nd], k);
            float vb = __shfl_sync(0xFFFFFFFFu, x1b[nd], k);
            xv4[nd] = fmaf(va, g0, xv4[nd]);
            xv4[nd] = fmaf(vb, g1, xv4[nd]);
        }
    }

#pragma unroll
    for (int nd = 0; nd < 4; nd++) {
        int n = nbase + nd;
        if (n >= NN) break;
        if (lane < CC) g_xl[n * CC + lane] = xv4[nd];
        float vs = (lane < CC) ? xv4[nd] * as_s[lane] : 0.f;
        float vd = (lane < CC) ? xv4[nd] * ad_s[lane] : 0.f;
#pragma unroll
        for (int o = 16; o > 0; o >>= 1) {
            vs += __shfl_down_sync(0xFFFFFFFFu, vs, o);
            vd += __shfl_down_sync(0xFFFFFFFFu, vd, o);
        }
        if (lane == 0) { g_asrc[n] = vs; g_adst[n] = vd; }
    }
}

// -------- GAT softmax-aggregate, single pass, smem (w,s) staging --------
__global__ void __launch_bounds__(256) k_gat(const int* __restrict__ src,
                                             const float* __restrict__ gbias) {
    __shared__ float bias_s[CC];
    __shared__ __align__(8) float2 sws[8][32];       // 2 KB
    int tid = threadIdx.x;
    if (tid < CC) bias_s[tid] = gbias[tid];
    __syncthreads();

    int wid = tid >> 5, lane = tid & 31;
    int n = (blockIdx.x * 256 + tid) >> 5;
    if (n >= NN) return;
    float asn = g_asrc[n], adn = g_adst[n];
    int beg = g_rowptr[n], end = g_rowptr[n + 1];

    float w0 = __expf(leaky(asn + adn));              // self loop
    float denom = (lane == 0) ? w0 : 0.f;
    float acc = (lane < CC) ? w0 * g_xl[n * CC + lane] : 0.f;
    for (int j0 = beg; j0 < end; j0 += 32) {
        int j = j0 + lane;
        int s = 0;
        float w = 0.f;
        if (j < end) {
            int e = g_eid[j];
            s = src[e];
            w = __expf(leaky(g_asrc[s] + adn));
        }
        denom += w;
        sws[wid][lane] = make_float2(w, __int_as_float(s));
        __syncwarp();
        int cnt = min(32, end - j0);
        for (int t = 0; t < cnt; t++) {
            float2 q = sws[wid][t];
            float wt = q.x;
            int st = __float_as_int(q.y);
            if (lane < CC) acc = fmaf(wt, g_xl[st * CC + lane], acc);
        }
        __syncwarp();
    }
#pragma unroll
    for (int o = 16; o > 0; o >>= 1) denom += __shfl_xor_sync(0xFFFFFFFFu, denom, o);
    if (lane < CC) g_x2[n * CC + lane] = fmaxf(acc / denom + bias_s[lane], 0.f);
}

// -------- fc1 (in-block zero compaction, 8-chain ILP) + fused fc2 via last-block --------
#define F1_ROWS 512
#define F1_GRID ((NN * CC + F1_ROWS - 1) / F1_ROWS)
__global__ void __launch_bounds__(512) k_fc1(const float* __restrict__ W,
                                             const float* __restrict__ fc1b,
                                             const float* __restrict__ W2,
                                             const float* __restrict__ b2,
                                             float* __restrict__ out) {
    __shared__ float sv[F1_ROWS];
    __shared__ int   sr[F1_ROWS];
    __shared__ int   wcnt[16];
    __shared__ int   woff[16];
    __shared__ int   sm_m;
    const int TOT = NN * CC;
    int tid = threadIdx.x;
    int lane = tid & 31, wid = tid >> 5;
    int r0 = blockIdx.x * F1_ROWS;

    int r = r0 + tid;
    float val = (r < TOT) ? g_x2[r] : 0.f;
    bool nz = (val > 0.f);
    unsigned m = __ballot_sync(0xFFFFFFFFu, nz);
    if (lane == 0) wcnt[wid] = __popc(m);
    __syncthreads();
    if (wid == 0 && lane < 16) {
        int c = wcnt[lane];
        int pv = c;
#pragma unroll
        for (int o = 1; o < 16; o <<= 1) {
            int t2 = __shfl_up_sync(0xFFFFu, pv, o);
            if (lane >= o) pv += t2;
        }
        woff[lane] = pv - c;
        if (lane == 15) sm_m = pv;
    }
    __syncthreads();
    if (nz) {
        int p = woff[wid] + __popc(m & ((1u << lane) - 1u));
        sv[p] = val;
        sr[p] = r;
    }
    __syncthreads();
    int mtot = sm_m;

    float a0 = 0.f, a1 = 0.f, a2 = 0.f, a3 = 0.f, a4 = 0.f, a5 = 0.f, a6 = 0.f, a7 = 0.f;
    if (tid < HID) {
        int k = 0;
        for (; k + 8 <= mtot; k += 8) {
            a0 = fmaf(sv[k],     W[(size_t)sr[k]     * HID + tid], a0);
            a1 = fmaf(sv[k + 1], W[(size_t)sr[k + 1] * HID + tid], a1);
            a2 = fmaf(sv[k + 2], W[(size_t)sr[k + 2] * HID + tid], a2);
            a3 = fmaf(sv[k + 3], W[(size_t)sr[k + 3] * HID + tid], a3);
            a4 = fmaf(sv[k + 4], W[(size_t)sr[k + 4] * HID + tid], a4);
            a5 = fmaf(sv[k + 5], W[(size_t)sr[k + 5] * HID + tid], a5);
            a6 = fmaf(sv[k + 6], W[(size_t)sr[k + 6] * HID + tid], a6);
            a7 = fmaf(sv[k + 7], W[(size_t)sr[k + 7] * HID + tid], a7);
        }
        for (; k < mtot; k++) a0 = fmaf(sv[k], W[(size_t)sr[k] * HID + tid], a0);
        float tot = ((a0 + a1) + (a2 + a3)) + ((a4 + a5) + (a6 + a7));
        if (tot != 0.f) atomicAdd(&g_h450[tid], tot);
    }

    __threadfence();
    __shared__ int s_last;
    __syncthreads();
    if (tid == 0) s_last = (atomicAdd(&g_tick2, 1) == F1_GRID - 1) ? 1 : 0;
    __syncthreads();
    if (!s_last) return;
    if (tid == 0) g_tick2 = 0;

    __shared__ float hs[HID];
    __shared__ float part[4][FDIM];
    if (tid < HID) hs[tid] = fmaxf(g_h450[tid] + fc1b[tid], 0.f);
    __syncthreads();
    int grp = tid >> 7;          // 0..3
    int t = tid & 127;
    int j0 = grp * 113;
    int j1 = min(j0 + 113, HID);
    float acc = 0.f;
    for (int j = j0; j < j1; j++) acc = fmaf(hs[j], W2[j * FDIM + t], acc);
    part[grp][t] = acc;
    __syncthreads();
    if (tid < FDIM) {
        float v = ((part[0][tid] + part[1][tid]) + (part[2][tid] + part[3][tid])) + b2[tid];
        out[tid] = fmaxf(v, 0.f);
    }
}

// ---------------- launch ----------------
extern "C" void kernel_launch(void* const* d_in, const int* in_sizes, int n_in,
                              void* d_out, int out_size) {
    const float* x       = (const float*)d_in[0];
    const int*   eidx    = (const int*)d_in[1];
    const float* eattr   = (const float*)d_in[2];
    const float* mlp_w1  = (const float*)d_in[3];
    const float* mlp_b1  = (const float*)d_in[4];
    const float* mlp_w2  = (const float*)d_in[5];
    const float* mlp_b2  = (const float*)d_in[6];
    const float* nn_root = (const float*)d_in[7];
    const float* nn_bias = (const float*)d_in[8];
    const float* gat_w   = (const float*)d_in[9];
    const float* att_src = (const float*)d_in[10];
    const float* att_dst = (const float*)d_in[11];
    const float* gat_b   = (const float*)d_in[12];
    const float* fc1_w   = (const float*)d_in[13];
    const float* fc1_b   = (const float*)d_in[14];
    const float* fc2_w   = (const float*)d_in[15];
    const float* fc2_b   = (const float*)d_in[16];
    float* out = (float*)d_out;

    const int* src = eidx;          // edge_index[0]
    const int* dst = eidx + NE;     // edge_index[1]

    k_hist<<<H_GRID, H_BLK>>>(dst);                       // + fused scan (last block)
    k_scatter<<<(NE / 4 + 255) / 256, 256>>>(dst);
    k_edgeagg<<<(NN * 32 + 255) / 256, 256>>>(src, x, eattr, mlp_w1, mlp_b1);
    k_x1gat<<<(NN / 32 + 1), 256>>>(x, mlp_w2, mlp_b2, nn_root, nn_bias,
                                    gat_w, att_src, att_dst);
    k_gat<<<(NN * 32 + 255) / 256, 256>>>(src, gat_b);
    k_fc1<<<F1_GRID, 512>>>(fc1_w, fc1_b, fc2_w, fc2_b, out);
}

// round 13
// speedup vs baseline: 3.3187x; 1.0160x over previous
#include <cuda_runtime.h>
#include <cstdint>
#include <cstddef>

#define NN   10000
#define NE   320000
#define FIN5 5
#define FOUT 64
#define CC   27
#define MLPH 32
#define HID  450
#define FDIM 128

// ---------------- scratch (static device globals; no allocation) ----------------
__device__ float g_pn[(size_t)NN * 160];
__device__ float g_sx[NN * FIN5];
__device__ float g_xl[NN * CC];
__device__ float g_asrc[NN];
__device__ float g_adst[NN];
__device__ float g_x2[NN * CC];
__device__ float g_h450[HID];
__device__ int   g_deg[NN];
__device__ int   g_rowptr[NN + 1];
__device__ int   g_pos[NN];
__device__ int   g_eid[NE];
__device__ int   g_tick1;                    // hist->scan ticket
__device__ int   g_tick2;                    // fc1->fc2 ticket

__device__ __forceinline__ float leaky(float v) { return v > 0.f ? v : 0.2f * v; }

// ---------------- hist (4 edges/thread, ILP) + fused scan in last block ----------------
#define H_BLK  1024
#define H_PER  4
#define H_GRID ((NE + H_BLK * H_PER - 1) / (H_BLK * H_PER))
__global__ void __launch_bounds__(1024) k_hist(const int* __restrict__ dst) {
    int base = (blockIdx.x * H_BLK + threadIdx.x) * H_PER;
    if (base + H_PER <= NE) {
        int4 d = *(const int4*)&dst[base];
        atomicAdd(&g_deg[d.x], 1);
        atomicAdd(&g_deg[d.y], 1);
        atomicAdd(&g_deg[d.z], 1);
        atomicAdd(&g_deg[d.w], 1);
    } else {
        for (int k = 0; k < H_PER; k++) {
            int i = base + k;
            if (i < NE) atomicAdd(&g_deg[dst[i]], 1);
        }
    }
    __threadfence();
    __shared__ int s_last;
    __syncthreads();
    if (threadIdx.x == 0) s_last = (atomicAdd(&g_tick1, 1) == H_GRID - 1) ? 1 : 0;
    __syncthreads();
    if (!s_last) return;
    if (threadIdx.x == 0) g_tick1 = 0;
    __threadfence();

    // ---- scan (1024 threads, 10/thread) ----
    const int CH = 10;
    int tid = threadIdx.x;
    int sb = tid * CH;
    int local[CH];
    int s = 0;
#pragma unroll
    for (int k = 0; k < CH; k++) {
        int idx = sb + k;
        int d = (idx < NN) ? g_deg[idx] : 0;
        local[k] = s;
        s += d;
    }
    int lane = tid & 31, wid = tid >> 5;
    int v = s;
#pragma unroll
    for (int o = 1; o < 32; o <<= 1) {
        int t = __shfl_up_sync(0xFFFFFFFFu, v, o);
        if (lane >= o) v += t;
    }
    __shared__ int ws[32];
    if (lane == 31) ws[wid] = v;
    __syncthreads();
    if (wid == 0) {
        int u = ws[lane];
#pragma unroll
        for (int o = 1; o < 32; o <<= 1) {
            int t = __shfl_up_sync(0xFFFFFFFFu, u, o);
            if (lane >= o) u += t;
        }
        ws[lane] = u;
    }
    __syncthreads();
    int excl = v - s + (wid > 0 ? ws[wid - 1] : 0);
#pragma unroll
    for (int k = 0; k < CH; k++) {
        int idx = sb + k;
        if (idx <= NN) {
            int val = excl + local[k];
            g_rowptr[idx] = val;
            if (idx < NN) g_pos[idx] = val;
        }
    }
    __syncthreads();
    for (int i = tid; i < NN; i += 1024) g_deg[i] = 0;
    if (tid < HID) g_h450[tid] = 0.f;
}

// ---------------- scatter (4 edges/thread, overlapped atomics) ----------------
__global__ void k_scatter(const int* __restrict__ dst) {
    int base = (blockIdx.x * blockDim.x + threadIdx.x) * 4;
    if (base + 4 <= NE) {
        int4 d = *(const int4*)&dst[base];
        int p0 = atomicAdd(&g_pos[d.x], 1);
        int p1 = atomicAdd(&g_pos[d.y], 1);
        int p2 = atomicAdd(&g_pos[d.z], 1);
        int p3 = atomicAdd(&g_pos[d.w], 1);
        g_eid[p0] = base;
        g_eid[p1] = base + 1;
        g_eid[p2] = base + 2;
        g_eid[p3] = base + 3;
    } else {
        for (int k = 0; k < 4; k++) {
            int i = base + k;
            if (i < NE) {
                int p = atomicAdd(&g_pos[dst[i]], 1);
                g_eid[p] = i;
            }
        }
    }
}

// ------- per-edge MLP + rank-1 reduce; smem record staging (2 MIO/edge) -------
__global__ void __launch_bounds__(256) k_edgeagg(const int* __restrict__ src,
                                                 const float* __restrict__ x,
                                                 const float* __restrict__ ea,
                                                 const float* __restrict__ w1,
                                                 const float* __restrict__ b1) {
    __shared__ __align__(16) float srec[8][32][8];   // 8 KB
    int tid = threadIdx.x;
    int wid = tid >> 5, lane = tid & 31;
    int n = (blockIdx.x * 256 + tid) >> 5;
    if (n >= NN) return;

    float w1a = w1[lane], w1b = w1[MLPH + lane], b1v = b1[lane];

    float a0 = 0.f, a1 = 0.f, a2 = 0.f, a3 = 0.f, a4 = 0.f;
    float s0 = 0.f, s1 = 0.f, s2 = 0.f, s3 = 0.f, s4 = 0.f;

    int beg = g_rowptr[n], end = g_rowptr[n + 1];
    for (int j0 = beg; j0 < end; j0 += 32) {
        int j = j0 + lane;
        float ax = 0.f, ay = 0.f, x0 = 0.f, x1v = 0.f, x2v = 0.f, x3v = 0.f, x4v = 0.f;
        if (j < end) {
            int e = g_eid[j];
            int sN = src[e];
            float2 eav = ((const float2*)ea)[e];
            ax = eav.x; ay = eav.y;
            const float* xp = x + sN * FIN5;
            x0 = xp[0]; x1v = xp[1]; x2v = xp[2]; x3v = xp[3]; x4v = xp[4];
        }
        s0 += x0; s1 += x1v; s2 += x2v; s3 += x3v; s4 += x4v;
        float4* rp = (float4*)&srec[wid][lane][0];
        rp[0] = make_float4(ax, ay, x0, x1v);
        rp[1] = make_float4(x2v, x3v, x4v, 0.f);
        __syncwarp();
        int cnt = min(32, end - j0);
        for (int t = 0; t < cnt; t++) {
            const float4* qp = (const float4*)&srec[wid][t][0];
            float4 q0 = qp[0];
            float4 q1 = qp[1];
            float h = fmaxf(fmaf(q0.x, w1a, fmaf(q0.y, w1b, b1v)), 0.f);
            a0 = fmaf(h, q0.z, a0);
            a1 = fmaf(h, q0.w, a1);
            a2 = fmaf(h, q1.x, a2);
            a3 = fmaf(h, q1.y, a3);
            a4 = fmaf(h, q1.z, a4);
        }
        __syncwarp();
    }

    float* p = &g_pn[(size_t)n * 160];
    p[0 * 32 + lane] = a0;
    p[1 * 32 + lane] = a1;
    p[2 * 32 + lane] = a2;
    p[3 * 32 + lane] = a3;
    p[4 * 32 + lane] = a4;

#pragma unroll
    for (int o = 16; o > 0; o >>= 1) {
        s0 += __shfl_xor_sync(0xFFFFFFFFu, s0, o);
        s1 += __shfl_xor_sync(0xFFFFFFFFu, s1, o);
        s2 += __shfl_xor_sync(0xFFFFFFFFu, s2, o);
        s3 += __shfl_xor_sync(0xFFFFFFFFu, s3, o);
        s4 += __shfl_xor_sync(0xFFFFFFFFu, s4, o);
    }
    if (lane == 0) {
        float* sx = &g_sx[n * FIN5];
        sx[0] = s0; sx[1] = s1; sx[2] = s2; sx[3] = s3; sx[4] = s4;
    }
}

// ---- fused x1/GAT-prep: 4 nodes/warp, smem p-staging + L1-resident W2 __ldg ----
__global__ void __launch_bounds__(128) k_x1gat(const float* __restrict__ x,
                                               const float* __restrict__ w2,
                                               const float* __restrict__ b2,
                                               const float* __restrict__ nr,
                                               const float* __restrict__ nb,
                                               const float* __restrict__ gw,
                                               const float* __restrict__ att_s,
                                               const float* __restrict__ att_d) {
    __shared__ __align__(8) float smp[4][4][FIN5][32];   // 10 KB  p-staging (lane = m)
    __shared__ float b2s[FIN5 * FOUT];
    __shared__ float nrs[FIN5 * FOUT];
    __shared__ float nbs[FOUT];
    __shared__ float gws[FOUT * CC];
    __shared__ float as_s[CC], ad_s[CC];
    int tid = threadIdx.x;
    for (int i = tid; i < FIN5 * FOUT; i += 128) { b2s[i] = b2[i]; nrs[i] = nr[i]; }
    if (tid < FOUT) nbs[tid] = nb[tid];
    for (int i = tid; i < FOUT * CC; i += 128) gws[i] = gw[i];
    if (tid < CC) { as_s[tid] = att_s[tid]; ad_s[tid] = att_d[tid]; }
    __syncthreads();

    int wid = tid >> 5, lane = tid & 31;
    int nbase = (blockIdx.x * 4 + wid) * 4;          // NN = 10000 = 625*16, no tail
    if (nbase >= NN) return;

    // load Pn rows for 4 nodes and stage in smem (lane = m index)
#pragma unroll
    for (int nd = 0; nd < 4; nd++) {
        int n = nbase + nd;
        const float* pr = &g_pn[(size_t)n * 160];
#pragma unroll
        for (int i = 0; i < FIN5; i++) smp[wid][nd][i][lane] = pr[i * 32 + lane];
    }
    __syncwarp();

    float acc0[4], acc1[4];
#pragma unroll
    for (int nd = 0; nd < 4; nd++) { acc0[nd] = nbs[lane]; acc1[nd] = nbs[32 + lane]; }

#pragma unroll
    for (int nd = 0; nd < 4; nd++) {
        int n = nbase + nd;
#pragma unroll
        for (int i = 0; i < FIN5; i++) {
            float xv = __ldg(&x[n * FIN5 + i]);
            float sxv = g_sx[n * FIN5 + i];
            acc0[nd] = fmaf(xv, nrs[i * FOUT + lane], acc0[nd]);
            acc1[nd] = fmaf(xv, nrs[i * FOUT + 32 + lane], acc1[nd]);
            acc0[nd] = fmaf(sxv, b2s[i * FOUT + lane], acc0[nd]);
            acc1[nd] = fmaf(sxv, b2s[i * FOUT + 32 + lane], acc1[nd]);
        }
    }

    // main contraction: W2 via __ldg (L1-resident, shared across 4 nodes),
    // p via uniform LDS.64 broadcast over m-pairs
#pragma unroll 1
    for (int m2 = 0; m2 < MLPH / 2; m2++) {
        int m0 = m2 * 2;
        float w0a[FIN5], w1a[FIN5], w0b[FIN5], w1b[FIN5];
#pragma unroll
        for (int i = 0; i < FIN5; i++) {
            const float* wr0 = &w2[(m0)     * (FIN5 * FOUT) + i * FOUT];
            const float* wr1 = &w2[(m0 + 1) * (FIN5 * FOUT) + i * FOUT];
            w0a[i] = __ldg(wr0 + lane);
            w1a[i] = __ldg(wr0 + 32 + lane);
            w0b[i] = __ldg(wr1 + lane);
            w1b[i] = __ldg(wr1 + 32 + lane);
        }
#pragma unroll
        for (int nd = 0; nd < 4; nd++) {
#pragma unroll
            for (int i = 0; i < FIN5; i++) {
                float2 pv = *(const float2*)&smp[wid][nd][i][m0];
                acc0[nd] = fmaf(pv.x, w0a[i], acc0[nd]);
                acc1[nd] = fmaf(pv.x, w1a[i], acc1[nd]);
                acc0[nd] = fmaf(pv.y, w0b[i], acc0[nd]);
                acc1[nd] = fmaf(pv.y, w1b[i], acc1[nd]);
            }
        }
    }

    float x1a[4], x1b[4];
#pragma unroll
    for (int nd = 0; nd < 4; nd++) {
        x1a[nd] = fmaxf(acc0[nd], 0.f);
        x1b[nd] = fmaxf(acc1[nd], 0.f);
    }

    // xl = x1 @ gat_w ; gws LDS hoisted over 4 nodes (shfl broadcast of x1)
    int cidx = lane % CC;
    float xv4[4] = {0.f, 0.f, 0.f, 0.f};
#pragma unroll 4
    for (int k = 0; k < 32; k++) {
        float g0 = gws[k * CC + cidx];
        float g1 = gws[(32 + k) * CC + cidx];
#pragma unroll
        for (int nd = 0; nd < 4; nd++) {
            float va = __shfl_sync(0xFFFFFFFFu, x1a[nd], k);
            float vb = __shfl_sync(0xFFFFFFFFu, x1b[nd], k);
            xv4[nd] = fmaf(va, g0, xv4[nd]);
            xv4[nd] = fmaf(vb, g1, xv4[nd]);
        }
    }

#pragma unroll
    for (int nd = 0; nd < 4; nd++) {
        int n = nbase + nd;
        if (lane < CC) g_xl[n * CC + lane] = xv4[nd];
        float vs = (lane < CC) ? xv4[nd] * as_s[lane] : 0.f;
        float vd = (lane < CC) ? xv4[nd] * ad_s[lane] : 0.f;
#pragma unroll
        for (int o = 16; o > 0; o >>= 1) {
            vs += __shfl_down_sync(0xFFFFFFFFu, vs, o);
            vd += __shfl_down_sync(0xFFFFFFFFu, vd, o);
        }
        if (lane == 0) { g_asrc[n] = vs; g_adst[n] = vd; }
    }
}

// -------- GAT softmax-aggregate, single pass, smem (w,s) staging --------
__global__ void __launch_bounds__(256) k_gat(const int* __restrict__ src,
                                             const float* __restrict__ gbias) {
    __shared__ float bias_s[CC];
    __shared__ __align__(8) float2 sws[8][32];       // 2 KB
    int tid = threadIdx.x;
    if (tid < CC) bias_s[tid] = gbias[tid];
    __syncthreads();

    int wid = tid >> 5, lane = tid & 31;
    int n = (blockIdx.x * 256 + tid) >> 5;
    if (n >= NN) return;
    float asn = g_asrc[n], adn = g_adst[n];
    int beg = g_rowptr[n], end = g_rowptr[n + 1];

    float w0 = __expf(leaky(asn + adn));              // self loop
    float denom = (lane == 0) ? w0 : 0.f;
    float acc = (lane < CC) ? w0 * g_xl[n * CC + lane] : 0.f;
    for (int j0 = beg; j0 < end; j0 += 32) {
        int j = j0 + lane;
        int s = 0;
        float w = 0.f;
        if (j < end) {
            int e = g_eid[j];
            s = src[e];
            w = __expf(leaky(g_asrc[s] + adn));
        }
        denom += w;
        sws[wid][lane] = make_float2(w, __int_as_float(s));
        __syncwarp();
        int cnt = min(32, end - j0);
        for (int t = 0; t < cnt; t++) {
            float2 q = sws[wid][t];
            float wt = q.x;
            int st = __float_as_int(q.y);
            if (lane < CC) acc = fmaf(wt, g_xl[st * CC + lane], acc);
        }
        __syncwarp();
    }
#pragma unroll
    for (int o = 16; o > 0; o >>= 1) denom += __shfl_xor_sync(0xFFFFFFFFu, denom, o);
    if (lane < CC) g_x2[n * CC + lane] = fmaxf(acc / denom + bias_s[lane], 0.f);
}

// -------- fc1 (in-block zero compaction, 8-chain ILP) + fused fc2 via last-block --------
#define F1_ROWS 512
#define F1_GRID ((NN * CC + F1_ROWS - 1) / F1_ROWS)
__global__ void __launch_bounds__(512) k_fc1(const float* __restrict__ W,
                                             const float* __restrict__ fc1b,
                                             const float* __restrict__ W2,
                                             const float* __restrict__ b2,
                                             float* __restrict__ out) {
    __shared__ float sv[F1_ROWS];
    __shared__ int   sr[F1_ROWS];
    __shared__ int   wcnt[16];
    __shared__ int   woff[16];
    __shared__ int   sm_m;
    const int TOT = NN * CC;
    int tid = threadIdx.x;
    int lane = tid & 31, wid = tid >> 5;
    int r0 = blockIdx.x * F1_ROWS;

    int r = r0 + tid;
    float val = (r < TOT) ? g_x2[r] : 0.f;
    bool nz = (val > 0.f);
    unsigned m = __ballot_sync(0xFFFFFFFFu, nz);
    if (lane == 0) wcnt[wid] = __popc(m);
    __syncthreads();
    if (wid == 0 && lane < 16) {
        int c = wcnt[lane];
        int pv = c;
#pragma unroll
        for (int o = 1; o < 16; o <<= 1) {
            int t2 = __shfl_up_sync(0xFFFFu, pv, o);
            if (lane >= o) pv += t2;
        }
        woff[lane] = pv - c;
        if (lane == 15) sm_m = pv;
    }
    __syncthreads();
    if (nz) {
        int p = woff[wid] + __popc(m & ((1u << lane) - 1u));
        sv[p] = val;
        sr[p] = r;
    }
    __syncthreads();
    int mtot = sm_m;

    float a0 = 0.f, a1 = 0.f, a2 = 0.f, a3 = 0.f, a4 = 0.f, a5 = 0.f, a6 = 0.f, a7 = 0.f;
    if (tid < HID) {
        int k = 0;
        for (; k + 8 <= mtot; k += 8) {
            a0 = fmaf(sv[k],     W[(size_t)sr[k]     * HID + tid], a0);
            a1 = fmaf(sv[k + 1], W[(size_t)sr[k + 1] * HID + tid], a1);
            a2 = fmaf(sv[k + 2], W[(size_t)sr[k + 2] * HID + tid], a2);
            a3 = fmaf(sv[k + 3], W[(size_t)sr[k + 3] * HID + tid], a3);
            a4 = fmaf(sv[k + 4], W[(size_t)sr[k + 4] * HID + tid], a4);
            a5 = fmaf(sv[k + 5], W[(size_t)sr[k + 5] * HID + tid], a5);
            a6 = fmaf(sv[k + 6], W[(size_t)sr[k + 6] * HID + tid], a6);
            a7 = fmaf(sv[k + 7], W[(size_t)sr[k + 7] * HID + tid], a7);
        }
        for (; k < mtot; k++) a0 = fmaf(sv[k], W[(size_t)sr[k] * HID + tid], a0);
        float tot = ((a0 + a1) + (a2 + a3)) + ((a4 + a5) + (a6 + a7));
        if (tot != 0.f) atomicAdd(&g_h450[tid], tot);
    }

    __threadfence();
    __shared__ int s_last;
    __syncthreads();
    if (tid == 0) s_last = (atomicAdd(&g_tick2, 1) == F1_GRID - 1) ? 1 : 0;
    __syncthreads();
    if (!s_last) return;
    if (tid == 0) g_tick2 = 0;

    __shared__ float hs[HID];
    __shared__ float part[4][FDIM];
    if (tid < HID) hs[tid] = fmaxf(g_h450[tid] + fc1b[tid], 0.f);
    __syncthreads();
    int grp = tid >> 7;          // 0..3
    int t = tid & 127;
    int j0 = grp * 113;
    int j1 = min(j0 + 113, HID);
    float acc = 0.f;
    for (int j = j0; j < j1; j++) acc = fmaf(hs[j], W2[j * FDIM + t], acc);
    part[grp][t] = acc;
    __syncthreads();
    if (tid < FDIM) {
        float v = ((part[0][tid] + part[1][tid]) + (part[2][tid] + part[3][tid])) + b2[tid];
        out[tid] = fmaxf(v, 0.f);
    }
}

// ---------------- launch ----------------
extern "C" void kernel_launch(void* const* d_in, const int* in_sizes, int n_in,
                              void* d_out, int out_size) {
    const float* x       = (const float*)d_in[0];
    const int*   eidx    = (const int*)d_in[1];
    const float* eattr   = (const float*)d_in[2];
    const float* mlp_w1  = (const float*)d_in[3];
    const float* mlp_b1  = (const float*)d_in[4];
    const float* mlp_w2  = (const float*)d_in[5];
    const float* mlp_b2  = (const float*)d_in[6];
    const float* nn_root = (const float*)d_in[7];
    const float* nn_bias = (const float*)d_in[8];
    const float* gat_w   = (const float*)d_in[9];
    const float* att_src = (const float*)d_in[10];
    const float* att_dst = (const float*)d_in[11];
    const float* gat_b   = (const float*)d_in[12];
    const float* fc1_w   = (const float*)d_in[13];
    const float* fc1_b   = (const float*)d_in[14];
    const float* fc2_w   = (const float*)d_in[15];
    const float* fc2_b   = (const float*)d_in[16];
    float* out = (float*)d_out;

    const int* src = eidx;          // edge_index[0]
    const int* dst = eidx + NE;     // edge_index[1]

    k_hist<<<H_GRID, H_BLK>>>(dst);                       // + fused scan (last block)
    k_scatter<<<(NE / 4 + 255) / 256, 256>>>(dst);
    k_edgeagg<<<(NN * 32 + 255) / 256, 256>>>(src, x, eattr, mlp_w1, mlp_b1);
    k_x1gat<<<NN / 16, 128>>>(x, mlp_w2, mlp_b2, nn_root, nn_bias,
                              gat_w, att_src, att_dst);
    k_gat<<<(NN * 32 + 255) / 256, 256>>>(src, gat_b);
    k_fc1<<<F1_GRID, 512>>>(fc1_w, fc1_b, fc2_w, fc2_b, out);
}